// round 13
// baseline (speedup 1.0000x reference)
#include <cuda_runtime.h>
#include <cuda_bf16.h>
#include <math.h>
#include <stdint.h>

#define NN 100000
#define EE 200000
#define GG 2000
#define DD 300
#define D2 600
#define LL 5
#define FT 512
#define MAXDEG 4
#define BN_EPS 1e-5f

#define SP300 152
#define SP600 304
#define SP512 256

// ---------------- scratch (device globals; no allocation) ----------------
__device__ float d_h[NN * DD];
__device__ int   d_counts[NN];
__device__ int   d_cursor[NN];
__device__ int   d_rowptr[NN + 1];
__device__ int   d_part[NN];
__device__ int   d_bsum[128];
__device__ int   d_eidx[EE];
__device__ int   d_gstart[GG + 1];
__device__ float d_stats[2 * DD];
__device__ float d_mu[DD];
__device__ float d_istd[DD];
__device__ float d_ginv[DD];
__device__ float d_gcoef[DD];
// split activations (packed bf16x2 hi/lo)
__device__ uint32_t d_aggh[NN * SP300], d_aggl[NN * SP300];
__device__ uint32_t d_hidh[NN * SP600], d_hidl[NN * SP600];
__device__ uint32_t d_hgh[GG * SP300],  d_hgl[GG * SP300];
__device__ uint32_t d_hfh[GG * SP512],  d_hfl[GG * SP512];
__device__ uint32_t d_tbh[GG * SP512],  d_tbl[GG * SP512];
// split weights [N][SP]
__device__ uint32_t d_bt0h[DD * SP300],          d_bt0l[DD * SP300];
__device__ uint32_t d_bt1h[LL * D2 * SP300],     d_bt1l[LL * D2 * SP300];
__device__ uint32_t d_bt2h[LL * DD * SP600],     d_bt2l[LL * DD * SP600];
__device__ uint32_t d_bt3h[FT * SP300],          d_bt3l[FT * SP300];
__device__ uint32_t d_bt4h[FT * SP512],          d_bt4l[FT * SP512];
__device__ uint32_t d_bt5h[(FT / 2) * SP512],    d_bt5l[(FT / 2) * SP512];

// ---------------- helpers ----------------
__device__ __forceinline__ uint32_t smem_u32(const void* p) {
    uint32_t a;
    asm("{ .reg .u64 t; cvta.to.shared.u64 t, %1; cvt.u32.u64 %0, t; }" : "=r"(a) : "l"(p));
    return a;
}
__device__ __forceinline__ void cp16(uint32_t dst, const void* src, int valid) {
    int sz = valid ? 16 : 0;
    asm volatile("cp.async.cg.shared.global [%0], [%1], 16, %2;" :: "r"(dst), "l"(src), "r"(sz) : "memory");
}
#define CP_COMMIT() asm volatile("cp.async.commit_group;" ::: "memory")
#define CP_WAIT(n)  asm volatile("cp.async.wait_group %0;" :: "n"(n) : "memory")

__device__ __forceinline__ void split2(float x0, float x1, uint32_t& hi, uint32_t& lo) {
    asm("cvt.rn.bf16x2.f32 %0, %1, %2;" : "=r"(hi) : "f"(x1), "f"(x0));
    float h0 = __uint_as_float(hi << 16);
    float h1 = __uint_as_float(hi & 0xFFFF0000u);
    float l0 = x0 - h0, l1 = x1 - h1;
    asm("cvt.rn.bf16x2.f32 %0, %1, %2;" : "=r"(lo) : "f"(l1), "f"(l0));
}
__device__ __forceinline__ void mma_bf16(float* c, const uint32_t* a, const uint32_t* b) {
    asm("mma.sync.aligned.m16n8k16.row.col.f32.bf16.bf16.f32 "
        "{%0,%1,%2,%3}, {%4,%5,%6,%7}, {%8,%9}, {%0,%1,%2,%3};"
        : "+f"(c[0]), "+f"(c[1]), "+f"(c[2]), "+f"(c[3])
        : "r"(a[0]), "r"(a[1]), "r"(a[2]), "r"(a[3]), "r"(b[0]), "r"(b[1]));
}

// ---------------- bf16x3 emulated-fp32 GEMM: 3-stage ring (+ optional fused BN stats) ----------------
#define SS 12
#define SM_CH 1536
#define G_STAGES 3
#define GEMM_SMEM (G_STAGES * 4 * SM_CH * 4)   // 73728 bytes

template <int WSTAT>
__global__ __launch_bounds__(256, 2) void gemm_mma_k(
    const uint32_t* __restrict__ Ah, const uint32_t* __restrict__ Al,
    const uint32_t* __restrict__ Bh, const uint32_t* __restrict__ Bl,
    const float* __restrict__ bias, const float* __restrict__ add,
    float* __restrict__ C, uint32_t* __restrict__ Oh, uint32_t* __restrict__ Ol,
    float* __restrict__ stats,
    int M, int Nc, int SP, int SPo, int relu, int has_add) {
    extern __shared__ uint32_t sm[];
    int tid = threadIdx.x, lane = tid & 31, wid = tid >> 5;
    int wm = wid & 1, wn = wid >> 1;
    int bnc = blockIdx.x * 128;
    int bm = blockIdx.y * 128;
    int nch = SP >> 3;

    float acc[4][4][4];
#pragma unroll
    for (int i = 0; i < 4; i++)
#pragma unroll
        for (int j = 0; j < 4; j++)
#pragma unroll
            for (int r = 0; r < 4; r++) acc[i][j][r] = 0.f;

    int lr = tid >> 1, lg = tid & 1;
    auto load_chunk = [&](int c, int s) {
        uint32_t* base = sm + s * 4 * SM_CH;
        int gu = c * 8 + lg * 4;
        int gr = bm + lr, br = bnc + lr;
        uint32_t off = smem_u32(base + lr * SS + lg * 4);
        int va = gr < M, vb = br < Nc;
        cp16(off,                 Ah + (size_t)gr * SP + gu, va);
        cp16(off + SM_CH * 4,     Al + (size_t)gr * SP + gu, va);
        cp16(off + 2 * SM_CH * 4, Bh + (size_t)br * SP + gu, vb);
        cp16(off + 3 * SM_CH * 4, Bl + (size_t)br * SP + gu, vb);
    };

    // prologue: 2 chunks in flight
    load_chunk(0, 0);
    CP_COMMIT();
    if (1 < nch) load_chunk(1, 1);
    CP_COMMIT();

    int row = lane >> 2, qc = lane & 3;
    for (int c = 0; c < nch; c++) {
        CP_WAIT(1);
        __syncthreads();
        {
            int n2 = c + 2;
            if (n2 < nch) load_chunk(n2, n2 % G_STAGES);
            CP_COMMIT();
        }
        uint32_t* base = sm + (c % G_STAGES) * 4 * SM_CH;
        uint32_t* sAh = base;
        uint32_t* sAl = base + SM_CH;
        uint32_t* sBh = base + 2 * SM_CH;
        uint32_t* sBl = base + 3 * SM_CH;
        uint32_t bfh[4][2], bfl[4][2];
#pragma unroll
        for (int nt = 0; nt < 4; nt++) {
            int n = wn * 32 + nt * 8 + row;
            bfh[nt][0] = sBh[n * SS + qc];
            bfh[nt][1] = sBh[n * SS + 4 + qc];
            bfl[nt][0] = sBl[n * SS + qc];
            bfl[nt][1] = sBl[n * SS + 4 + qc];
        }
#pragma unroll
        for (int mt = 0; mt < 4; mt++) {
            int r0 = wm * 64 + mt * 16 + row;
            uint32_t ah[4], al[4];
            ah[0] = sAh[r0 * SS + qc];       ah[1] = sAh[(r0 + 8) * SS + qc];
            ah[2] = sAh[r0 * SS + 4 + qc];   ah[3] = sAh[(r0 + 8) * SS + 4 + qc];
            al[0] = sAl[r0 * SS + qc];       al[1] = sAl[(r0 + 8) * SS + qc];
            al[2] = sAl[r0 * SS + 4 + qc];   al[3] = sAl[(r0 + 8) * SS + 4 + qc];
#pragma unroll
            for (int nt = 0; nt < 4; nt++) mma_bf16(acc[mt][nt], ah, bfl[nt]);
#pragma unroll
            for (int nt = 0; nt < 4; nt++) mma_bf16(acc[mt][nt], al, bfh[nt]);
#pragma unroll
            for (int nt = 0; nt < 4; nt++) mma_bf16(acc[mt][nt], ah, bfh[nt]);
        }
    }

    // epilogue (ls/lq live only here — post-k-loop register pressure window)
    float ls[WSTAT ? 8 : 1], lq[WSTAT ? 8 : 1];
    if (WSTAT) {
#pragma unroll
        for (int t = 0; t < 8; t++) { ls[t] = 0.f; lq[t] = 0.f; }
    }
#pragma unroll
    for (int mt = 0; mt < 4; mt++) {
#pragma unroll
        for (int nt = 0; nt < 4; nt++) {
#pragma unroll
            for (int half = 0; half < 2; half++) {
                int gr = bm + wm * 64 + mt * 16 + row + half * 8;
                if (gr >= M) continue;
                int gc0 = bnc + wn * 32 + nt * 8 + qc * 2;
                if (gc0 >= Nc) continue;
                float v0 = acc[mt][nt][half * 2 + 0] + bias[gc0];
                float v1 = acc[mt][nt][half * 2 + 1] + bias[gc0 + 1];
                if (has_add) {
                    v0 += add[(size_t)gr * Nc + gc0];
                    v1 += add[(size_t)gr * Nc + gc0 + 1];
                }
                if (relu) { v0 = fmaxf(v0, 0.f); v1 = fmaxf(v1, 0.f); }
                if (C) {
                    C[(size_t)gr * Nc + gc0] = v0;
                    C[(size_t)gr * Nc + gc0 + 1] = v1;
                }
                if (Oh) {
                    uint32_t hi, lo;
                    split2(v0, v1, hi, lo);
                    int p = gc0 >> 1;
                    Oh[(size_t)gr * SPo + p] = hi;
                    Ol[(size_t)gr * SPo + p] = lo;
                }
                if (WSTAT) {
                    ls[nt * 2 + 0] += v0;  lq[nt * 2 + 0] += v0 * v0;
                    ls[nt * 2 + 1] += v1;  lq[nt * 2 + 1] += v1 * v1;
                }
            }
        }
    }
    if (WSTAT) {
        __syncthreads();                 // all warps done reading stage smem
        float* ssum = (float*)sm;
        float* ssq = ssum + 128;
        ((float*)sm)[tid] = 0.f;         // zero ssum+ssq (256 floats)
        __syncthreads();
#pragma unroll
        for (int t = 0; t < 8; t++) {
            int lc = wn * 32 + (t >> 1) * 8 + qc * 2 + (t & 1);
            atomicAdd(&ssum[lc], ls[t]);
            atomicAdd(&ssq[lc], lq[t]);
        }
        __syncthreads();
        if (tid < 128) {
            int gc = bnc + tid;
            if (gc < Nc) {
                atomicAdd(&stats[gc], ssum[tid]);
                atomicAdd(&stats[Nc + gc], ssq[tid]);
            }
        }
    }
}

// ---------------- fused weight prep ----------------
struct PrepSeg { const float* w; uint32_t* oh; uint32_t* ol; int K, N, SP; };
struct PrepArgs { PrepSeg s[14]; };

__global__ void prep_all_k(PrepArgs a) {
    PrepSeg p = a.s[blockIdx.y];
    int idx = blockIdx.x * blockDim.x + threadIdx.x;
    if (idx >= p.N * p.SP) return;
    int n = idx / p.SP, ku = idx % p.SP;
    int k0 = ku * 2, k1 = k0 + 1;
    float x0 = (k0 < p.K) ? p.w[(size_t)k0 * p.N + n] : 0.f;
    float x1 = (k1 < p.K) ? p.w[(size_t)k1 * p.N + n] : 0.f;
    uint32_t hi, lo;
    split2(x0, x1, hi, lo);
    p.oh[idx] = hi;
    p.ol[idx] = lo;
}

// ---------------- misc ----------------
__global__ void zero_i(int* p, int n) {
    int i = blockIdx.x * blockDim.x + threadIdx.x;
    if (i < n) p[i] = 0;
}
__global__ void count_k(const int* __restrict__ dst, int* counts) {
    int e = blockIdx.x * blockDim.x + threadIdx.x;
    if (e < EE) atomicAdd(&counts[dst[e]], 1);
}

// ---------------- CSR build ----------------
__global__ void scan1_k(const int* __restrict__ counts, int* part, int* bsum) {
    __shared__ int sh[1024];
    int tid = threadIdx.x;
    int i = blockIdx.x * 1024 + tid;
    int v = (i < NN) ? counts[i] : 0;
    sh[tid] = v;
    __syncthreads();
#pragma unroll
    for (int off = 1; off < 1024; off <<= 1) {
        int t = (tid >= off) ? sh[tid - off] : 0;
        __syncthreads();
        sh[tid] += t;
        __syncthreads();
    }
    if (i < NN) part[i] = sh[tid] - v;
    if (tid == 1023) bsum[blockIdx.x] = sh[1023];
}
__global__ void scan2_k(int* bsum, int nb) {
    if (threadIdx.x == 0 && blockIdx.x == 0) {
        int run = 0;
        for (int b = 0; b < nb; b++) { int t = bsum[b]; bsum[b] = run; run += t; }
    }
}
__global__ void scan3_k(const int* __restrict__ part, const int* __restrict__ bsum, int* rowptr) {
    int i = blockIdx.x * blockDim.x + threadIdx.x;
    if (i < NN) rowptr[i] = part[i] + bsum[i >> 10];
    if (i == 0) rowptr[NN] = EE;
}
__global__ void fill_k(const int* __restrict__ dst, const int* __restrict__ rowptr,
                       int* cursor, int* eidx) {
    int e = blockIdx.x * blockDim.x + threadIdx.x;
    if (e >= EE) return;
    int d = dst[e];
    int pos = atomicAdd(&cursor[d], 1);
    eidx[rowptr[d] + pos] = e;
}

// ---------------- gaussian basis: adds into h ----------------
__global__ void gauss_pre_k(const float* __restrict__ g_stds, float* ginv, float* gcoef) {
    int d = blockIdx.x * blockDim.x + threadIdx.x;
    if (d < DD) {
        float s = fabsf(g_stds[d]) + 0.01f;
        float a = sqrtf(2.0f * 3.14159f);
        ginv[d] = 1.f / s;
        gcoef[d] = 1.f / (a * s);
    }
}
__global__ void gauss_csr_k(const float* __restrict__ dist, const int* __restrict__ rowptr,
                            const int* __restrict__ eidx,
                            const float* __restrict__ g_means,
                            const float* __restrict__ ginv, const float* __restrict__ gcoef,
                            const float* __restrict__ scale_param, float* __restrict__ h) {
    int n = (blockIdx.x * blockDim.x + threadIdx.x) >> 5;
    int lane = threadIdx.x & 31;
    if (n >= NN) return;
    int beg = rowptr[n], end = rowptr[n + 1];
    int degc = min(max(end - beg - 1, 0), MAXDEG - 1);
    float gm[10], gi[10], gc[10], acc[10];
#pragma unroll
    for (int c = 0; c < 10; c++) {
        int d = c * 32 + lane;
        acc[c] = 0.f;
        if (d < DD) { gm[c] = g_means[d]; gi[c] = ginv[d]; gc[c] = gcoef[d]; }
    }
    for (int j = beg; j < end; j++) {
        float de = dist[eidx[j]];
#pragma unroll
        for (int c = 0; c < 10; c++) {
            int d = c * 32 + lane;
            if (d < DD) {
                float z = (de - gm[c]) * gi[c];
                acc[c] += __expf(-0.5f * z * z) * gc[c];
            }
        }
    }
    const float* sp = scale_param + degc * DD;
#pragma unroll
    for (int c = 0; c < 10; c++) {
        int d = c * 32 + lane;
        if (d < DD) h[(size_t)n * DD + d] += acc[c] * expf(sp[d]);
    }
}

// ---------------- attention fusion -> split "fused" ----------------
__global__ void attn_k(const int* __restrict__ x, const float* __restrict__ atom_emb,
                       const float* __restrict__ att_vec,
                       uint32_t* __restrict__ fh, uint32_t* __restrict__ fl) {
    int warp = (blockIdx.x * blockDim.x + threadIdx.x) >> 5;
    int lane = threadIdx.x & 31;
    if (warp >= NN) return;
    const int* xn = x + warp * 9;
    const float2* emb2 = (const float2*)atom_emb;
    const float2* av2 = (const float2*)att_vec;
    int ids[9];
#pragma unroll
    for (int f = 0; f < 9; f++) ids[f] = (f * 119 + xn[f]) * 150;
    float sc[9];
#pragma unroll
    for (int f = 0; f < 9; f++) {
        float p = 0.f;
        for (int pc = lane; pc < 150; pc += 32) {
            float2 e = emb2[ids[f] + pc];
            float2 a = av2[pc];
            p += e.x * a.x + e.y * a.y;
        }
#pragma unroll
        for (int o = 16; o > 0; o >>= 1) p += __shfl_xor_sync(0xffffffffu, p, o);
        sc[f] = p;
    }
    float m = sc[0];
#pragma unroll
    for (int f = 1; f < 9; f++) m = fmaxf(m, sc[f]);
    float s = 0.f;
#pragma unroll
    for (int f = 0; f < 9; f++) { sc[f] = __expf(sc[f] - m); s += sc[f]; }
    float inv = 1.f / s;
    for (int pc = lane; pc < 150; pc += 32) {
        float2 a = make_float2(0.f, 0.f);
#pragma unroll
        for (int f = 0; f < 9; f++) {
            float2 e = emb2[ids[f] + pc];
            a.x += sc[f] * e.x;
            a.y += sc[f] * e.y;
        }
        uint32_t hi, lo;
        split2(a.x * inv, a.y * inv, hi, lo);
        fh[(size_t)warp * SP300 + pc] = hi;
        fl[(size_t)warp * SP300 + pc] = lo;
    }
}

// ---------------- CSR aggregation with inline BN(+relu) ----------------
__global__ void gather_k(const float* __restrict__ h,
                         const int* __restrict__ rowptr, const int* __restrict__ eidx,
                         const int* __restrict__ src, const int* __restrict__ attr,
                         const float* __restrict__ E0, const float* __restrict__ E1,
                         const float* __restrict__ E2,
                         const float* __restrict__ mu, const float* __restrict__ istd,
                         const float* __restrict__ gamma, const float* __restrict__ beta,
                         int apply_bn,
                         uint32_t* __restrict__ aggh, uint32_t* __restrict__ aggl) {
    int n = (blockIdx.x * blockDim.x + threadIdx.x) >> 5;
    int lane = threadIdx.x & 31;
    if (n >= NN) return;
    int beg = rowptr[n], end = rowptr[n + 1];
    const float2* h2 = (const float2*)h;
    const float2* e02 = (const float2*)(E0 + 4 * DD);
    const float2* e12 = (const float2*)E1;
    const float2* e22 = (const float2*)E2;

    float2 scv[5], shv[5];
#pragma unroll
    for (int c = 0; c < 5; c++) {
        int pc = c * 32 + lane;
        if (pc < 150 && apply_bn) {
            float2 g = ((const float2*)gamma)[pc];
            float2 b = ((const float2*)beta)[pc];
            float2 m = ((const float2*)mu)[pc];
            float2 is = ((const float2*)istd)[pc];
            scv[c].x = g.x * is.x; scv[c].y = g.y * is.y;
            shv[c].x = b.x - m.x * scv[c].x; shv[c].y = b.y - m.y * scv[c].y;
        }
    }

    float2 acc[5];
#pragma unroll
    for (int c = 0; c < 5; c++) {
        int pc = c * 32 + lane;
        if (pc < 150) {
            float2 v = h2[(size_t)n * 150 + pc];
            if (apply_bn) {
                v.x = fmaxf(v.x * scv[c].x + shv[c].x, 0.f);
                v.y = fmaxf(v.y * scv[c].y + shv[c].y, 0.f);
            }
            float2 s0 = e02[pc], s1 = e12[pc], s2 = e22[pc];
            acc[c].x = v.x + s0.x + s1.x + s2.x;
            acc[c].y = v.y + s0.y + s1.y + s2.y;
        }
    }
    for (int j = beg; j < end; j++) {
        int e = eidx[j];
        int s = src[e];
        int a0 = attr[e * 3 + 0], a1 = attr[e * 3 + 1], a2 = attr[e * 3 + 2];
        const float2* hs = h2 + (size_t)s * 150;
        const float2* p0 = (const float2*)(E0 + a0 * DD);
        const float2* p1 = (const float2*)(E1 + a1 * DD);
        const float2* p2 = (const float2*)(E2 + a2 * DD);
#pragma unroll
        for (int c = 0; c < 5; c++) {
            int pc = c * 32 + lane;
            if (pc < 150) {
                float2 v = hs[pc];
                if (apply_bn) {
                    v.x = fmaxf(v.x * scv[c].x + shv[c].x, 0.f);
                    v.y = fmaxf(v.y * scv[c].y + shv[c].y, 0.f);
                }
                float2 q0 = p0[pc], q1 = p1[pc], q2 = p2[pc];
                acc[c].x += v.x + q0.x + q1.x + q2.x;
                acc[c].y += v.y + q0.y + q1.y + q2.y;
            }
        }
    }
#pragma unroll
    for (int c = 0; c < 5; c++) {
        int pc = c * 32 + lane;
        if (pc < 150) {
            uint32_t hi, lo;
            split2(acc[c].x, acc[c].y, hi, lo);
            aggh[(size_t)n * SP300 + pc] = hi;
            aggl[(size_t)n * SP300 + pc] = lo;
        }
    }
}

// ---------------- bn finalize (stats -> mu/istd, re-zero stats) ----------------
__global__ void bn_fin_k(const float* __restrict__ stats, float* mu, float* istd, float* stats_z) {
    int d = blockIdx.x * blockDim.x + threadIdx.x;
    if (d < DD) {
        float m = stats[d] / (float)NN;
        float v = stats[DD + d] / (float)NN - m * m;
        v = fmaxf(v, 0.f);
        mu[d] = m;
        istd[d] = rsqrtf(v + BN_EPS);
        stats_z[d] = 0.f;
        stats_z[DD + d] = 0.f;
    }
}

// ---------------- pooling with inline BN (last layer) ----------------
__global__ void gstart_k(const int* __restrict__ batch, int* gstart) {
    int g = blockIdx.x * blockDim.x + threadIdx.x;
    if (g > GG) return;
    int lo = 0, hi = NN;
    while (lo < hi) {
        int mid = (lo + hi) >> 1;
        if (batch[mid] < g) lo = mid + 1; else hi = mid;
    }
    gstart[g] = lo;
}
__global__ void pool_k(const float* __restrict__ h, const int* __restrict__ gstart,
                       const float* __restrict__ mu, const float* __restrict__ istd,
                       const float* __restrict__ gamma, const float* __restrict__ beta,
                       uint32_t* __restrict__ hgh, uint32_t* __restrict__ hgl) {
    int g = blockIdx.x;
    int pc = threadIdx.x;
    if (pc >= 150) return;
    const float2* h2 = (const float2*)h;
    float2 gm = ((const float2*)gamma)[pc];
    float2 bt = ((const float2*)beta)[pc];
    float2 m = ((const float2*)mu)[pc];
    float2 is = ((const float2*)istd)[pc];
    float2 sc, sh;
    sc.x = gm.x * is.x; sc.y = gm.y * is.y;
    sh.x = bt.x - m.x * sc.x; sh.y = bt.y - m.y * sc.y;
    int s = gstart[g], e = gstart[g + 1];
    float2 a = make_float2(0.f, 0.f);
    for (int r = s; r < e; r++) {
        float2 v = h2[(size_t)r * 150 + pc];
        a.x += v.x * sc.x + sh.x;
        a.y += v.y * sc.y + sh.y;
    }
    float inv = 1.f / fmaxf((float)(e - s), 1.f);
    uint32_t hi, lo;
    split2(a.x * inv, a.y * inv, hi, lo);
    hgh[(size_t)g * SP300 + pc] = hi;
    hgl[(size_t)g * SP300 + pc] = lo;
}

// ---------------- host ----------------
static float* symf(const void* sym) { void* p = nullptr; cudaGetSymbolAddress(&p, sym); return (float*)p; }
static int* symi(const void* sym) { void* p = nullptr; cudaGetSymbolAddress(&p, sym); return (int*)p; }
static uint32_t* symu(const void* sym) { void* p = nullptr; cudaGetSymbolAddress(&p, sym); return (uint32_t*)p; }
static inline int cdiv(int a, int b) { return (a + b - 1) / b; }

extern "C" void kernel_launch(void* const* d_in, const int* in_sizes, int n_in,
                              void* d_out, int out_size) {
    const int* x            = (const int*)d_in[0];
    const int* edge_index   = (const int*)d_in[1];
    const int* edge_attr    = (const int*)d_in[2];
    const float* edge_dist  = (const float*)d_in[3];
    const int* batch        = (const int*)d_in[4];
    const float* atom_emb   = (const float*)d_in[5];
    const float* att_vec    = (const float*)d_in[6];
    const float* out_lin_w  = (const float*)d_in[7];
    const float* out_lin_b  = (const float*)d_in[8];
    const float* g_means    = (const float*)d_in[9];
    const float* g_stds     = (const float*)d_in[10];
    const float* scale_par  = (const float*)d_in[11];
    const float* edge_emb   = (const float*)d_in[12];
    const float* mlp_w1     = (const float*)d_in[13];
    const float* mlp_b1     = (const float*)d_in[14];
    const float* mlp_w2     = (const float*)d_in[15];
    const float* mlp_b2     = (const float*)d_in[16];
    const float* bn_gamma   = (const float*)d_in[17];
    const float* bn_beta    = (const float*)d_in[18];
    const float* feat_w     = (const float*)d_in[19];
    const float* feat_b     = (const float*)d_in[20];
    const float* ol_w1      = (const float*)d_in[21];
    const float* ol_b1      = (const float*)d_in[22];
    const float* ol_w2      = (const float*)d_in[23];
    const float* ol_b2      = (const float*)d_in[24];

    const int* e_src = edge_index;
    const int* e_dst = edge_index + EE;

    float* h      = symf(d_h);
    int*   counts = symi(d_counts);
    int*   cursor = symi(d_cursor);
    int*   rowptr = symi(d_rowptr);
    int*   part   = symi(d_part);
    int*   bsum   = symi(d_bsum);
    int*   eidx   = symi(d_eidx);
    int*   gstart = symi(d_gstart);
    float* stats  = symf(d_stats);
    float* mu     = symf(d_mu);
    float* istd   = symf(d_istd);
    float* ginv   = symf(d_ginv);
    float* gcoef  = symf(d_gcoef);
    uint32_t* aggh = symu(d_aggh), *aggl = symu(d_aggl);
    uint32_t* hidh = symu(d_hidh), *hidl = symu(d_hidl);
    uint32_t* hgh = symu(d_hgh), *hgl = symu(d_hgl);
    uint32_t* hfh = symu(d_hfh), *hfl = symu(d_hfl);
    uint32_t* tbh = symu(d_tbh), *tbl = symu(d_tbl);
    uint32_t* bt0h = symu(d_bt0h), *bt0l = symu(d_bt0l);
    uint32_t* bt1h = symu(d_bt1h), *bt1l = symu(d_bt1l);
    uint32_t* bt2h = symu(d_bt2h), *bt2l = symu(d_bt2l);
    uint32_t* bt3h = symu(d_bt3h), *bt3l = symu(d_bt3l);
    uint32_t* bt4h = symu(d_bt4h), *bt4l = symu(d_bt4l);
    uint32_t* bt5h = symu(d_bt5h), *bt5l = symu(d_bt5l);

    float* out_hfeat = (float*)d_out;
    float* out_final = (float*)d_out + GG * FT;

    const int T = 256;
    cudaFuncSetAttribute(gemm_mma_k<0>, cudaFuncAttributeMaxDynamicSharedMemorySize, GEMM_SMEM);
    cudaFuncSetAttribute(gemm_mma_k<1>, cudaFuncAttributeMaxDynamicSharedMemorySize, GEMM_SMEM);

    // launch 1: fused weight prep
    {
        PrepArgs pa;
        pa.s[0] = { out_lin_w, bt0h, bt0l, DD, DD, SP300 };
        for (int l = 0; l < LL; l++) {
            pa.s[1 + l] = { mlp_w1 + (size_t)l * DD * D2,
                            bt1h + (size_t)l * D2 * SP300, bt1l + (size_t)l * D2 * SP300,
                            DD, D2, SP300 };
            pa.s[6 + l] = { mlp_w2 + (size_t)l * D2 * DD,
                            bt2h + (size_t)l * DD * SP600, bt2l + (size_t)l * DD * SP600,
                            D2, DD, SP600 };
        }
        pa.s[11] = { feat_w, bt3h, bt3l, DD, FT, SP300 };
        pa.s[12] = { ol_w1, bt4h, bt4l, FT, FT, SP512 };
        pa.s[13] = { ol_w2, bt5h, bt5l, FT, FT / 2, SP512 };
        dim3 g(cdiv(FT * SP512, T), 14);
        prep_all_k<<<g, T>>>(pa);
    }
    // launch 2: attention fusion
    attn_k<<<cdiv(NN * 32, T), T>>>(x, atom_emb, att_vec, aggh, aggl);
    // launch 3
    zero_i<<<cdiv(NN, T), T>>>(counts, NN);
    // launch 4 (ncu sample target): layer-0 GEMM
    {
        dim3 g(cdiv(DD, 128), cdiv(NN, 128));
        gemm_mma_k<0><<<g, 256, GEMM_SMEM>>>(aggh, aggl, bt0h, bt0l, out_lin_b, nullptr,
                                             h, nullptr, nullptr, nullptr,
                                             NN, DD, SP300, 0, 0, 0);
    }
    // CSR build
    count_k<<<cdiv(EE, T), T>>>(e_dst, counts);
    scan1_k<<<cdiv(NN, 1024), 1024>>>(counts, part, bsum);
    scan2_k<<<1, 32>>>(bsum, cdiv(NN, 1024));
    scan3_k<<<cdiv(NN, T), T>>>(part, bsum, rowptr);
    zero_i<<<cdiv(NN, T), T>>>(cursor, NN);
    fill_k<<<cdiv(EE, T), T>>>(e_dst, rowptr, cursor, eidx);
    // gaussian basis adds into h
    gauss_pre_k<<<cdiv(DD, T), T>>>(g_stds, ginv, gcoef);
    gauss_csr_k<<<cdiv(NN * 32, T), T>>>(edge_dist, rowptr, eidx, g_means, ginv, gcoef,
                                         scale_par, h);

    // --- L layers ---
    for (int l = 0; l < LL; l++) {
        const float* E0 = edge_emb + (size_t)(l * 3 + 0) * 5 * DD;
        const float* E1 = edge_emb + (size_t)(l * 3 + 1) * 5 * DD;
        const float* E2 = edge_emb + (size_t)(l * 3 + 2) * 5 * DD;
        gather_k<<<cdiv(NN * 32, T), T>>>(h, rowptr, eidx, e_src, edge_attr, E0, E1, E2,
                                          mu, istd, bn_gamma + (l - 1) * DD, bn_beta + (l - 1) * DD,
                                          (l > 0) ? 1 : 0, aggh, aggl);
        {
            dim3 g1(cdiv(D2, 128), cdiv(NN, 128));
            gemm_mma_k<0><<<g1, 256, GEMM_SMEM>>>(aggh, aggl,
                                                  bt1h + (size_t)l * D2 * SP300,
                                                  bt1l + (size_t)l * D2 * SP300,
                                                  mlp_b1 + l * D2, nullptr,
                                                  nullptr, hidh, hidl, nullptr,
                                                  NN, D2, SP300, SP600, 1, 0);
            dim3 g2(cdiv(DD, 128), cdiv(NN, 128));
            gemm_mma_k<1><<<g2, 256, GEMM_SMEM>>>(hidh, hidl,
                                                  bt2h + (size_t)l * DD * SP600,
                                                  bt2l + (size_t)l * DD * SP600,
                                                  mlp_b2 + l * DD, nullptr,
                                                  h, nullptr, nullptr, stats,
                                                  NN, DD, SP600, 0, 0, 0);
        }
        bn_fin_k<<<cdiv(DD, T), T>>>(stats, mu, istd, stats);
    }

    // --- pooling with inline BN of last layer ---
    gstart_k<<<cdiv(GG + 1, T), T>>>(batch, gstart);
    pool_k<<<GG, 160>>>(h, gstart, mu, istd, bn_gamma + (LL - 1) * DD, bn_beta + (LL - 1) * DD,
                        hgh, hgl);

    // --- head ---
    {
        dim3 g(cdiv(FT, 128), cdiv(GG, 128));
        gemm_mma_k<0><<<g, 256, GEMM_SMEM>>>(hgh, hgl, bt3h, bt3l, feat_b, nullptr,
                                             out_hfeat, hfh, hfl, nullptr,
                                             GG, FT, SP300, SP512, 0, 0);
    }
    {
        dim3 g(cdiv(FT, 128), cdiv(GG, 128));
        gemm_mma_k<0><<<g, 256, GEMM_SMEM>>>(hfh, hfl, bt4h, bt4l, ol_b1, nullptr,
                                             nullptr, tbh, tbl, nullptr,
                                             GG, FT, SP512, SP512, 1, 0);
    }
    {
        dim3 g(cdiv(FT / 2, 128), cdiv(GG, 128));
        gemm_mma_k<0><<<g, 256, GEMM_SMEM>>>(tbh, tbl, bt5h, bt5l, ol_b2, nullptr,
                                             out_final, nullptr, nullptr, nullptr,
                                             GG, FT / 2, SP512, 0, 0, 0);
    }
}

// round 14
// speedup vs baseline: 1.0208x; 1.0208x over previous
#include <cuda_runtime.h>
#include <cuda_bf16.h>
#include <math.h>
#include <stdint.h>

#define NN 100000
#define EE 200000
#define GG 2000
#define DD 300
#define D2 600
#define LL 5
#define FT 512
#define MAXDEG 4
#define BN_EPS 1e-5f

#define SP300 152
#define SP600 304
#define SP512 256

// ---------------- scratch (device globals; no allocation) ----------------
__device__ float d_h[NN * DD];
__device__ int   d_counts[NN];
__device__ int   d_cursor[NN];
__device__ int   d_rowptr[NN + 1];
__device__ int   d_part[NN];
__device__ int   d_bsum[128];
__device__ int   d_eidx[EE];
__device__ int   d_gstart[GG + 1];
__device__ float d_stats[2 * DD];
__device__ float d_mu[DD];
__device__ float d_istd[DD];
__device__ float d_ginv[DD];
__device__ float d_gcoef[DD];
// split activations (packed bf16x2 hi/lo)
__device__ uint32_t d_aggh[NN * SP300], d_aggl[NN * SP300];
__device__ uint32_t d_hidh[NN * SP600], d_hidl[NN * SP600];
__device__ uint32_t d_hgh[GG * SP300],  d_hgl[GG * SP300];
__device__ uint32_t d_hfh[GG * SP512],  d_hfl[GG * SP512];
__device__ uint32_t d_tbh[GG * SP512],  d_tbl[GG * SP512];
// split weights [N][SP]
__device__ uint32_t d_bt0h[DD * SP300],          d_bt0l[DD * SP300];
__device__ uint32_t d_bt1h[LL * D2 * SP300],     d_bt1l[LL * D2 * SP300];
__device__ uint32_t d_bt2h[LL * DD * SP600],     d_bt2l[LL * DD * SP600];
__device__ uint32_t d_bt3h[FT * SP300],          d_bt3l[FT * SP300];
__device__ uint32_t d_bt4h[FT * SP512],          d_bt4l[FT * SP512];
__device__ uint32_t d_bt5h[(FT / 2) * SP512],    d_bt5l[(FT / 2) * SP512];

// ---------------- helpers ----------------
__device__ __forceinline__ uint32_t smem_u32(const void* p) {
    uint32_t a;
    asm("{ .reg .u64 t; cvta.to.shared.u64 t, %1; cvt.u32.u64 %0, t; }" : "=r"(a) : "l"(p));
    return a;
}
__device__ __forceinline__ void cp16(uint32_t dst, const void* src, int valid) {
    int sz = valid ? 16 : 0;
    asm volatile("cp.async.cg.shared.global [%0], [%1], 16, %2;" :: "r"(dst), "l"(src), "r"(sz) : "memory");
}
#define CP_COMMIT() asm volatile("cp.async.commit_group;" ::: "memory")
#define CP_WAIT(n)  asm volatile("cp.async.wait_group %0;" :: "n"(n) : "memory")

__device__ __forceinline__ void split2(float x0, float x1, uint32_t& hi, uint32_t& lo) {
    asm("cvt.rn.bf16x2.f32 %0, %1, %2;" : "=r"(hi) : "f"(x1), "f"(x0));
    float h0 = __uint_as_float(hi << 16);
    float h1 = __uint_as_float(hi & 0xFFFF0000u);
    float l0 = x0 - h0, l1 = x1 - h1;
    asm("cvt.rn.bf16x2.f32 %0, %1, %2;" : "=r"(lo) : "f"(l1), "f"(l0));
}
__device__ __forceinline__ void mma_bf16(float* c, const uint32_t* a, const uint32_t* b) {
    asm("mma.sync.aligned.m16n8k16.row.col.f32.bf16.bf16.f32 "
        "{%0,%1,%2,%3}, {%4,%5,%6,%7}, {%8,%9}, {%0,%1,%2,%3};"
        : "+f"(c[0]), "+f"(c[1]), "+f"(c[2]), "+f"(c[3])
        : "r"(a[0]), "r"(a[1]), "r"(a[2]), "r"(a[3]), "r"(b[0]), "r"(b[1]));
}

// ---------------- bf16x3 emulated-fp32 GEMM ----------------
// 128 threads = 4 warps (2x2), BM=128, BN=64, warp tile 64x32, 3-stage ring.
// 4 blocks/SM (regs capped at 128 by launch_bounds).
#define SS 12
#define A_CH 1536            // 128 rows * 12 u32
#define B_CH 768             // 64 rows * 12 u32
#define ST_CH (2 * A_CH + 2 * B_CH)   // 4608 u32 per stage
#define G_STAGES 3
#define GEMM_SMEM (G_STAGES * ST_CH * 4)   // 55296 bytes

__global__ __launch_bounds__(128, 4) void gemm_mma_k(
    const uint32_t* __restrict__ Ah, const uint32_t* __restrict__ Al,
    const uint32_t* __restrict__ Bh, const uint32_t* __restrict__ Bl,
    const float* __restrict__ bias, const float* __restrict__ add,
    float* __restrict__ C, uint32_t* __restrict__ Oh, uint32_t* __restrict__ Ol,
    int M, int Nc, int SP, int SPo, int relu, int has_add) {
    extern __shared__ uint32_t sm[];
    int tid = threadIdx.x, lane = tid & 31, wid = tid >> 5;
    int wm = wid & 1, wn = wid >> 1;      // 2 x 2 warp grid
    int bnc = blockIdx.x * 64;
    int bm = blockIdx.y * 128;
    int nch = SP >> 3;

    float acc[4][4][4];
#pragma unroll
    for (int i = 0; i < 4; i++)
#pragma unroll
        for (int j = 0; j < 4; j++)
#pragma unroll
            for (int r = 0; r < 4; r++) acc[i][j][r] = 0.f;

    auto load_chunk = [&](int c, int s) {
        uint32_t* base = sm + s * ST_CH;
        int gu = c * 8;
        // A: 128 rows x 2 granules (256 slots, 128 threads -> 2 iters)
#pragma unroll
        for (int it = 0; it < 2; it++) {
            int i = tid + it * 128;
            int r = i >> 1, g = i & 1;
            int gr = bm + r;
            uint32_t off = smem_u32(base + r * SS + g * 4);
            int va = gr < M;
            cp16(off,            Ah + (size_t)gr * SP + gu + g * 4, va);
            cp16(off + A_CH * 4, Al + (size_t)gr * SP + gu + g * 4, va);
        }
        // B: 64 rows x 2 granules (128 slots, 1 iter)
        {
            int r = tid >> 1, g = tid & 1;
            int br = bnc + r;
            uint32_t off = smem_u32(base + 2 * A_CH + r * SS + g * 4);
            int vb = br < Nc;
            cp16(off,            Bh + (size_t)br * SP + gu + g * 4, vb);
            cp16(off + B_CH * 4, Bl + (size_t)br * SP + gu + g * 4, vb);
        }
    };

    // prologue: 2 chunks in flight
    load_chunk(0, 0);
    CP_COMMIT();
    if (1 < nch) load_chunk(1, 1);
    CP_COMMIT();

    int row = lane >> 2, qc = lane & 3;
    for (int c = 0; c < nch; c++) {
        CP_WAIT(1);
        __syncthreads();
        {
            int n2 = c + 2;
            if (n2 < nch) load_chunk(n2, n2 % G_STAGES);
            CP_COMMIT();
        }
        uint32_t* base = sm + (c % G_STAGES) * ST_CH;
        uint32_t* sAh = base;
        uint32_t* sAl = base + A_CH;
        uint32_t* sBh = base + 2 * A_CH;
        uint32_t* sBl = base + 2 * A_CH + B_CH;
        uint32_t bfh[4][2], bfl[4][2];
#pragma unroll
        for (int nt = 0; nt < 4; nt++) {
            int n = wn * 32 + nt * 8 + row;
            bfh[nt][0] = sBh[n * SS + qc];
            bfh[nt][1] = sBh[n * SS + 4 + qc];
            bfl[nt][0] = sBl[n * SS + qc];
            bfl[nt][1] = sBl[n * SS + 4 + qc];
        }
#pragma unroll
        for (int mt = 0; mt < 4; mt++) {
            int r0 = wm * 64 + mt * 16 + row;
            uint32_t ah[4], al[4];
            ah[0] = sAh[r0 * SS + qc];       ah[1] = sAh[(r0 + 8) * SS + qc];
            ah[2] = sAh[r0 * SS + 4 + qc];   ah[3] = sAh[(r0 + 8) * SS + 4 + qc];
            al[0] = sAl[r0 * SS + qc];       al[1] = sAl[(r0 + 8) * SS + qc];
            al[2] = sAl[r0 * SS + 4 + qc];   al[3] = sAl[(r0 + 8) * SS + 4 + qc];
#pragma unroll
            for (int nt = 0; nt < 4; nt++) mma_bf16(acc[mt][nt], ah, bfl[nt]);
#pragma unroll
            for (int nt = 0; nt < 4; nt++) mma_bf16(acc[mt][nt], al, bfh[nt]);
#pragma unroll
            for (int nt = 0; nt < 4; nt++) mma_bf16(acc[mt][nt], ah, bfh[nt]);
        }
    }

    // epilogue
#pragma unroll
    for (int mt = 0; mt < 4; mt++) {
#pragma unroll
        for (int nt = 0; nt < 4; nt++) {
#pragma unroll
            for (int half = 0; half < 2; half++) {
                int gr = bm + wm * 64 + mt * 16 + row + half * 8;
                if (gr >= M) continue;
                int gc0 = bnc + wn * 32 + nt * 8 + qc * 2;
                if (gc0 >= Nc) continue;
                float v0 = acc[mt][nt][half * 2 + 0] + bias[gc0];
                float v1 = acc[mt][nt][half * 2 + 1] + bias[gc0 + 1];
                if (has_add) {
                    v0 += add[(size_t)gr * Nc + gc0];
                    v1 += add[(size_t)gr * Nc + gc0 + 1];
                }
                if (relu) { v0 = fmaxf(v0, 0.f); v1 = fmaxf(v1, 0.f); }
                if (C) {
                    C[(size_t)gr * Nc + gc0] = v0;
                    C[(size_t)gr * Nc + gc0 + 1] = v1;
                }
                if (Oh) {
                    uint32_t hi, lo;
                    split2(v0, v1, hi, lo);
                    int p = gc0 >> 1;
                    Oh[(size_t)gr * SPo + p] = hi;
                    Ol[(size_t)gr * SPo + p] = lo;
                }
            }
        }
    }
}

// ---------------- fused weight prep ----------------
struct PrepSeg { const float* w; uint32_t* oh; uint32_t* ol; int K, N, SP; };
struct PrepArgs { PrepSeg s[14]; };

__global__ void prep_all_k(PrepArgs a) {
    PrepSeg p = a.s[blockIdx.y];
    int idx = blockIdx.x * blockDim.x + threadIdx.x;
    if (idx >= p.N * p.SP) return;
    int n = idx / p.SP, ku = idx % p.SP;
    int k0 = ku * 2, k1 = k0 + 1;
    float x0 = (k0 < p.K) ? p.w[(size_t)k0 * p.N + n] : 0.f;
    float x1 = (k1 < p.K) ? p.w[(size_t)k1 * p.N + n] : 0.f;
    uint32_t hi, lo;
    split2(x0, x1, hi, lo);
    p.oh[idx] = hi;
    p.ol[idx] = lo;
}

// ---------------- misc ----------------
__global__ void zero_i(int* p, int n) {
    int i = blockIdx.x * blockDim.x + threadIdx.x;
    if (i < n) p[i] = 0;
}
__global__ void count_k(const int* __restrict__ dst, int* counts) {
    int e = blockIdx.x * blockDim.x + threadIdx.x;
    if (e < EE) atomicAdd(&counts[dst[e]], 1);
}

// ---------------- CSR build ----------------
__global__ void scan1_k(const int* __restrict__ counts, int* part, int* bsum) {
    __shared__ int sh[1024];
    int tid = threadIdx.x;
    int i = blockIdx.x * 1024 + tid;
    int v = (i < NN) ? counts[i] : 0;
    sh[tid] = v;
    __syncthreads();
#pragma unroll
    for (int off = 1; off < 1024; off <<= 1) {
        int t = (tid >= off) ? sh[tid - off] : 0;
        __syncthreads();
        sh[tid] += t;
        __syncthreads();
    }
    if (i < NN) part[i] = sh[tid] - v;
    if (tid == 1023) bsum[blockIdx.x] = sh[1023];
}
__global__ void scan2_k(int* bsum, int nb) {
    if (threadIdx.x == 0 && blockIdx.x == 0) {
        int run = 0;
        for (int b = 0; b < nb; b++) { int t = bsum[b]; bsum[b] = run; run += t; }
    }
}
__global__ void scan3_k(const int* __restrict__ part, const int* __restrict__ bsum, int* rowptr) {
    int i = blockIdx.x * blockDim.x + threadIdx.x;
    if (i < NN) rowptr[i] = part[i] + bsum[i >> 10];
    if (i == 0) rowptr[NN] = EE;
}
__global__ void fill_k(const int* __restrict__ dst, const int* __restrict__ rowptr,
                       int* cursor, int* eidx) {
    int e = blockIdx.x * blockDim.x + threadIdx.x;
    if (e >= EE) return;
    int d = dst[e];
    int pos = atomicAdd(&cursor[d], 1);
    eidx[rowptr[d] + pos] = e;
}

// ---------------- gaussian basis: adds into h ----------------
__global__ void gauss_pre_k(const float* __restrict__ g_stds, float* ginv, float* gcoef) {
    int d = blockIdx.x * blockDim.x + threadIdx.x;
    if (d < DD) {
        float s = fabsf(g_stds[d]) + 0.01f;
        float a = sqrtf(2.0f * 3.14159f);
        ginv[d] = 1.f / s;
        gcoef[d] = 1.f / (a * s);
    }
}
__global__ void gauss_csr_k(const float* __restrict__ dist, const int* __restrict__ rowptr,
                            const int* __restrict__ eidx,
                            const float* __restrict__ g_means,
                            const float* __restrict__ ginv, const float* __restrict__ gcoef,
                            const float* __restrict__ scale_param, float* __restrict__ h) {
    int n = (blockIdx.x * blockDim.x + threadIdx.x) >> 5;
    int lane = threadIdx.x & 31;
    if (n >= NN) return;
    int beg = rowptr[n], end = rowptr[n + 1];
    int degc = min(max(end - beg - 1, 0), MAXDEG - 1);
    float gm[10], gi[10], gc[10], acc[10];
#pragma unroll
    for (int c = 0; c < 10; c++) {
        int d = c * 32 + lane;
        acc[c] = 0.f;
        if (d < DD) { gm[c] = g_means[d]; gi[c] = ginv[d]; gc[c] = gcoef[d]; }
    }
    for (int j = beg; j < end; j++) {
        float de = dist[eidx[j]];
#pragma unroll
        for (int c = 0; c < 10; c++) {
            int d = c * 32 + lane;
            if (d < DD) {
                float z = (de - gm[c]) * gi[c];
                acc[c] += __expf(-0.5f * z * z) * gc[c];
            }
        }
    }
    const float* sp = scale_param + degc * DD;
#pragma unroll
    for (int c = 0; c < 10; c++) {
        int d = c * 32 + lane;
        if (d < DD) h[(size_t)n * DD + d] += acc[c] * expf(sp[d]);
    }
}

// ---------------- attention fusion -> split "fused" ----------------
__global__ void attn_k(const int* __restrict__ x, const float* __restrict__ atom_emb,
                       const float* __restrict__ att_vec,
                       uint32_t* __restrict__ fh, uint32_t* __restrict__ fl) {
    int warp = (blockIdx.x * blockDim.x + threadIdx.x) >> 5;
    int lane = threadIdx.x & 31;
    if (warp >= NN) return;
    const int* xn = x + warp * 9;
    const float2* emb2 = (const float2*)atom_emb;
    const float2* av2 = (const float2*)att_vec;
    int ids[9];
#pragma unroll
    for (int f = 0; f < 9; f++) ids[f] = (f * 119 + xn[f]) * 150;
    float sc[9];
#pragma unroll
    for (int f = 0; f < 9; f++) {
        float p = 0.f;
        for (int pc = lane; pc < 150; pc += 32) {
            float2 e = emb2[ids[f] + pc];
            float2 a = av2[pc];
            p += e.x * a.x + e.y * a.y;
        }
#pragma unroll
        for (int o = 16; o > 0; o >>= 1) p += __shfl_xor_sync(0xffffffffu, p, o);
        sc[f] = p;
    }
    float m = sc[0];
#pragma unroll
    for (int f = 1; f < 9; f++) m = fmaxf(m, sc[f]);
    float s = 0.f;
#pragma unroll
    for (int f = 0; f < 9; f++) { sc[f] = __expf(sc[f] - m); s += sc[f]; }
    float inv = 1.f / s;
    for (int pc = lane; pc < 150; pc += 32) {
        float2 a = make_float2(0.f, 0.f);
#pragma unroll
        for (int f = 0; f < 9; f++) {
            float2 e = emb2[ids[f] + pc];
            a.x += sc[f] * e.x;
            a.y += sc[f] * e.y;
        }
        uint32_t hi, lo;
        split2(a.x * inv, a.y * inv, hi, lo);
        fh[(size_t)warp * SP300 + pc] = hi;
        fl[(size_t)warp * SP300 + pc] = lo;
    }
}

// ---------------- CSR aggregation with inline BN(+relu) ----------------
__global__ void gather_k(const float* __restrict__ h,
                         const int* __restrict__ rowptr, const int* __restrict__ eidx,
                         const int* __restrict__ src, const int* __restrict__ attr,
                         const float* __restrict__ E0, const float* __restrict__ E1,
                         const float* __restrict__ E2,
                         const float* __restrict__ mu, const float* __restrict__ istd,
                         const float* __restrict__ gamma, const float* __restrict__ beta,
                         int apply_bn,
                         uint32_t* __restrict__ aggh, uint32_t* __restrict__ aggl) {
    int n = (blockIdx.x * blockDim.x + threadIdx.x) >> 5;
    int lane = threadIdx.x & 31;
    if (n >= NN) return;
    int beg = rowptr[n], end = rowptr[n + 1];
    const float2* h2 = (const float2*)h;
    const float2* e02 = (const float2*)(E0 + 4 * DD);
    const float2* e12 = (const float2*)E1;
    const float2* e22 = (const float2*)E2;

    float2 scv[5], shv[5];
#pragma unroll
    for (int c = 0; c < 5; c++) {
        int pc = c * 32 + lane;
        if (pc < 150 && apply_bn) {
            float2 g = ((const float2*)gamma)[pc];
            float2 b = ((const float2*)beta)[pc];
            float2 m = ((const float2*)mu)[pc];
            float2 is = ((const float2*)istd)[pc];
            scv[c].x = g.x * is.x; scv[c].y = g.y * is.y;
            shv[c].x = b.x - m.x * scv[c].x; shv[c].y = b.y - m.y * scv[c].y;
        }
    }

    float2 acc[5];
#pragma unroll
    for (int c = 0; c < 5; c++) {
        int pc = c * 32 + lane;
        if (pc < 150) {
            float2 v = h2[(size_t)n * 150 + pc];
            if (apply_bn) {
                v.x = fmaxf(v.x * scv[c].x + shv[c].x, 0.f);
                v.y = fmaxf(v.y * scv[c].y + shv[c].y, 0.f);
            }
            float2 s0 = e02[pc], s1 = e12[pc], s2 = e22[pc];
            acc[c].x = v.x + s0.x + s1.x + s2.x;
            acc[c].y = v.y + s0.y + s1.y + s2.y;
        }
    }
    for (int j = beg; j < end; j++) {
        int e = eidx[j];
        int s = src[e];
        int a0 = attr[e * 3 + 0], a1 = attr[e * 3 + 1], a2 = attr[e * 3 + 2];
        const float2* hs = h2 + (size_t)s * 150;
        const float2* p0 = (const float2*)(E0 + a0 * DD);
        const float2* p1 = (const float2*)(E1 + a1 * DD);
        const float2* p2 = (const float2*)(E2 + a2 * DD);
#pragma unroll
        for (int c = 0; c < 5; c++) {
            int pc = c * 32 + lane;
            if (pc < 150) {
                float2 v = hs[pc];
                if (apply_bn) {
                    v.x = fmaxf(v.x * scv[c].x + shv[c].x, 0.f);
                    v.y = fmaxf(v.y * scv[c].y + shv[c].y, 0.f);
                }
                float2 q0 = p0[pc], q1 = p1[pc], q2 = p2[pc];
                acc[c].x += v.x + q0.x + q1.x + q2.x;
                acc[c].y += v.y + q0.y + q1.y + q2.y;
            }
        }
    }
#pragma unroll
    for (int c = 0; c < 5; c++) {
        int pc = c * 32 + lane;
        if (pc < 150) {
            uint32_t hi, lo;
            split2(acc[c].x, acc[c].y, hi, lo);
            aggh[(size_t)n * SP300 + pc] = hi;
            aggl[(size_t)n * SP300 + pc] = lo;
        }
    }
}

// ---------------- batchnorm ----------------
#define BN_RPB 128
__global__ void bn_stats_k(const float* __restrict__ h, float* stats) {
    int row0 = blockIdx.x * BN_RPB;
    int rend = min(row0 + BN_RPB, NN);
    int c0 = threadIdx.x;
    int c1 = threadIdx.x + 256;
    float s0 = 0.f, q0 = 0.f, s1 = 0.f, q1 = 0.f;
    for (int r = row0; r < rend; r++) {
        float v0 = h[(size_t)r * DD + c0];
        s0 += v0; q0 += v0 * v0;
        if (c1 < DD) {
            float v1 = h[(size_t)r * DD + c1];
            s1 += v1; q1 += v1 * v1;
        }
    }
    atomicAdd(&stats[c0], s0);
    atomicAdd(&stats[DD + c0], q0);
    if (c1 < DD) {
        atomicAdd(&stats[c1], s1);
        atomicAdd(&stats[DD + c1], q1);
    }
}
__global__ void bn_fin_k(const float* __restrict__ stats, float* mu, float* istd, float* stats_z) {
    int d = blockIdx.x * blockDim.x + threadIdx.x;
    if (d < DD) {
        float m = stats[d] / (float)NN;
        float v = stats[DD + d] / (float)NN - m * m;
        v = fmaxf(v, 0.f);
        mu[d] = m;
        istd[d] = rsqrtf(v + BN_EPS);
        stats_z[d] = 0.f;
        stats_z[DD + d] = 0.f;
    }
}

// ---------------- pooling with inline BN (last layer) ----------------
__global__ void gstart_k(const int* __restrict__ batch, int* gstart) {
    int g = blockIdx.x * blockDim.x + threadIdx.x;
    if (g > GG) return;
    int lo = 0, hi = NN;
    while (lo < hi) {
        int mid = (lo + hi) >> 1;
        if (batch[mid] < g) lo = mid + 1; else hi = mid;
    }
    gstart[g] = lo;
}
__global__ void pool_k(const float* __restrict__ h, const int* __restrict__ gstart,
                       const float* __restrict__ mu, const float* __restrict__ istd,
                       const float* __restrict__ gamma, const float* __restrict__ beta,
                       uint32_t* __restrict__ hgh, uint32_t* __restrict__ hgl) {
    int g = blockIdx.x;
    int pc = threadIdx.x;
    if (pc >= 150) return;
    const float2* h2 = (const float2*)h;
    float2 gm = ((const float2*)gamma)[pc];
    float2 bt = ((const float2*)beta)[pc];
    float2 m = ((const float2*)mu)[pc];
    float2 is = ((const float2*)istd)[pc];
    float2 sc, sh;
    sc.x = gm.x * is.x; sc.y = gm.y * is.y;
    sh.x = bt.x - m.x * sc.x; sh.y = bt.y - m.y * sc.y;
    int s = gstart[g], e = gstart[g + 1];
    float2 a = make_float2(0.f, 0.f);
    for (int r = s; r < e; r++) {
        float2 v = h2[(size_t)r * 150 + pc];
        a.x += v.x * sc.x + sh.x;
        a.y += v.y * sc.y + sh.y;
    }
    float inv = 1.f / fmaxf((float)(e - s), 1.f);
    uint32_t hi, lo;
    split2(a.x * inv, a.y * inv, hi, lo);
    hgh[(size_t)g * SP300 + pc] = hi;
    hgl[(size_t)g * SP300 + pc] = lo;
}

// ---------------- host ----------------
static float* symf(const void* sym) { void* p = nullptr; cudaGetSymbolAddress(&p, sym); return (float*)p; }
static int* symi(const void* sym) { void* p = nullptr; cudaGetSymbolAddress(&p, sym); return (int*)p; }
static uint32_t* symu(const void* sym) { void* p = nullptr; cudaGetSymbolAddress(&p, sym); return (uint32_t*)p; }
static inline int cdiv(int a, int b) { return (a + b - 1) / b; }

extern "C" void kernel_launch(void* const* d_in, const int* in_sizes, int n_in,
                              void* d_out, int out_size) {
    const int* x            = (const int*)d_in[0];
    const int* edge_index   = (const int*)d_in[1];
    const int* edge_attr    = (const int*)d_in[2];
    const float* edge_dist  = (const float*)d_in[3];
    const int* batch        = (const int*)d_in[4];
    const float* atom_emb   = (const float*)d_in[5];
    const float* att_vec    = (const float*)d_in[6];
    const float* out_lin_w  = (const float*)d_in[7];
    const float* out_lin_b  = (const float*)d_in[8];
    const float* g_means    = (const float*)d_in[9];
    const float* g_stds     = (const float*)d_in[10];
    const float* scale_par  = (const float*)d_in[11];
    const float* edge_emb   = (const float*)d_in[12];
    const float* mlp_w1     = (const float*)d_in[13];
    const float* mlp_b1     = (const float*)d_in[14];
    const float* mlp_w2     = (const float*)d_in[15];
    const float* mlp_b2     = (const float*)d_in[16];
    const float* bn_gamma   = (const float*)d_in[17];
    const float* bn_beta    = (const float*)d_in[18];
    const float* feat_w     = (const float*)d_in[19];
    const float* feat_b     = (const float*)d_in[20];
    const float* ol_w1      = (const float*)d_in[21];
    const float* ol_b1      = (const float*)d_in[22];
    const float* ol_w2      = (const float*)d_in[23];
    const float* ol_b2      = (const float*)d_in[24];

    const int* e_src = edge_index;
    const int* e_dst = edge_index + EE;

    float* h      = symf(d_h);
    int*   counts = symi(d_counts);
    int*   cursor = symi(d_cursor);
    int*   rowptr = symi(d_rowptr);
    int*   part   = symi(d_part);
    int*   bsum   = symi(d_bsum);
    int*   eidx   = symi(d_eidx);
    int*   gstart = symi(d_gstart);
    float* stats  = symf(d_stats);
    float* mu     = symf(d_mu);
    float* istd   = symf(d_istd);
    float* ginv   = symf(d_ginv);
    float* gcoef  = symf(d_gcoef);
    uint32_t* aggh = symu(d_aggh), *aggl = symu(d_aggl);
    uint32_t* hidh = symu(d_hidh), *hidl = symu(d_hidl);
    uint32_t* hgh = symu(d_hgh), *hgl = symu(d_hgl);
    uint32_t* hfh = symu(d_hfh), *hfl = symu(d_hfl);
    uint32_t* tbh = symu(d_tbh), *tbl = symu(d_tbl);
    uint32_t* bt0h = symu(d_bt0h), *bt0l = symu(d_bt0l);
    uint32_t* bt1h = symu(d_bt1h), *bt1l = symu(d_bt1l);
    uint32_t* bt2h = symu(d_bt2h), *bt2l = symu(d_bt2l);
    uint32_t* bt3h = symu(d_bt3h), *bt3l = symu(d_bt3l);
    uint32_t* bt4h = symu(d_bt4h), *bt4l = symu(d_bt4l);
    uint32_t* bt5h = symu(d_bt5h), *bt5l = symu(d_bt5l);

    float* out_hfeat = (float*)d_out;
    float* out_final = (float*)d_out + GG * FT;

    const int T = 256;
    cudaFuncSetAttribute(gemm_mma_k, cudaFuncAttributeMaxDynamicSharedMemorySize, GEMM_SMEM);

    // launch 1: fused weight prep
    {
        PrepArgs pa;
        pa.s[0] = { out_lin_w, bt0h, bt0l, DD, DD, SP300 };
        for (int l = 0; l < LL; l++) {
            pa.s[1 + l] = { mlp_w1 + (size_t)l * DD * D2,
                            bt1h + (size_t)l * D2 * SP300, bt1l + (size_t)l * D2 * SP300,
                            DD, D2, SP300 };
            pa.s[6 + l] = { mlp_w2 + (size_t)l * D2 * DD,
                            bt2h + (size_t)l * DD * SP600, bt2l + (size_t)l * DD * SP600,
                            D2, DD, SP600 };
        }
        pa.s[11] = { feat_w, bt3h, bt3l, DD, FT, SP300 };
        pa.s[12] = { ol_w1, bt4h, bt4l, FT, FT, SP512 };
        pa.s[13] = { ol_w2, bt5h, bt5l, FT, FT / 2, SP512 };
        dim3 g(cdiv(FT * SP512, T), 14);
        prep_all_k<<<g, T>>>(pa);
    }
    // launch 2: attention fusion
    attn_k<<<cdiv(NN * 32, T), T>>>(x, atom_emb, att_vec, aggh, aggl);
    // launch 3
    zero_i<<<cdiv(NN, T), T>>>(counts, NN);
    // launch 4 (ncu sample target): layer-0 GEMM
    {
        dim3 g(cdiv(DD, 64), cdiv(NN, 128));
        gemm_mma_k<<<g, 128, GEMM_SMEM>>>(aggh, aggl, bt0h, bt0l, out_lin_b, nullptr,
                                          h, nullptr, nullptr, NN, DD, SP300, 0, 0, 0);
    }
    // CSR build
    count_k<<<cdiv(EE, T), T>>>(e_dst, counts);
    scan1_k<<<cdiv(NN, 1024), 1024>>>(counts, part, bsum);
    scan2_k<<<1, 32>>>(bsum, cdiv(NN, 1024));
    scan3_k<<<cdiv(NN, T), T>>>(part, bsum, rowptr);
    zero_i<<<cdiv(NN, T), T>>>(cursor, NN);
    fill_k<<<cdiv(EE, T), T>>>(e_dst, rowptr, cursor, eidx);
    // gaussian basis adds into h
    gauss_pre_k<<<cdiv(DD, T), T>>>(g_stds, ginv, gcoef);
    gauss_csr_k<<<cdiv(NN * 32, T), T>>>(edge_dist, rowptr, eidx, g_means, ginv, gcoef,
                                         scale_par, h);

    // --- L layers ---
    for (int l = 0; l < LL; l++) {
        const float* E0 = edge_emb + (size_t)(l * 3 + 0) * 5 * DD;
        const float* E1 = edge_emb + (size_t)(l * 3 + 1) * 5 * DD;
        const float* E2 = edge_emb + (size_t)(l * 3 + 2) * 5 * DD;
        gather_k<<<cdiv(NN * 32, T), T>>>(h, rowptr, eidx, e_src, edge_attr, E0, E1, E2,
                                          mu, istd, bn_gamma + (l - 1) * DD, bn_beta + (l - 1) * DD,
                                          (l > 0) ? 1 : 0, aggh, aggl);
        {
            dim3 g1(cdiv(D2, 64), cdiv(NN, 128));
            gemm_mma_k<<<g1, 128, GEMM_SMEM>>>(aggh, aggl,
                                               bt1h + (size_t)l * D2 * SP300,
                                               bt1l + (size_t)l * D2 * SP300,
                                               mlp_b1 + l * D2, nullptr,
                                               nullptr, hidh, hidl, NN, D2, SP300, SP600, 1, 0);
            dim3 g2(cdiv(DD, 64), cdiv(NN, 128));
            gemm_mma_k<<<g2, 128, GEMM_SMEM>>>(hidh, hidl,
                                               bt2h + (size_t)l * DD * SP600,
                                               bt2l + (size_t)l * DD * SP600,
                                               mlp_b2 + l * DD, nullptr,
                                               h, nullptr, nullptr, NN, DD, SP600, 0, 0, 0);
        }
        bn_stats_k<<<cdiv(NN, BN_RPB), 256>>>(h, stats);
        bn_fin_k<<<cdiv(DD, T), T>>>(stats, mu, istd, stats);
    }

    // --- pooling with inline BN of last layer ---
    gstart_k<<<cdiv(GG + 1, T), T>>>(batch, gstart);
    pool_k<<<GG, 160>>>(h, gstart, mu, istd, bn_gamma + (LL - 1) * DD, bn_beta + (LL - 1) * DD,
                        hgh, hgl);

    // --- head ---
    {
        dim3 g(cdiv(FT, 64), cdiv(GG, 128));
        gemm_mma_k<<<g, 128, GEMM_SMEM>>>(hgh, hgl, bt3h, bt3l, feat_b, nullptr,
                                          out_hfeat, hfh, hfl, GG, FT, SP300, SP512, 0, 0);
    }
    {
        dim3 g(cdiv(FT, 64), cdiv(GG, 128));
        gemm_mma_k<<<g, 128, GEMM_SMEM>>>(hfh, hfl, bt4h, bt4l, ol_b1, nullptr,
                                          nullptr, tbh, tbl, GG, FT, SP512, SP512, 1, 0);
    }
    {
        dim3 g(cdiv(FT / 2, 64), cdiv(GG, 128));
        gemm_mma_k<<<g, 128, GEMM_SMEM>>>(tbh, tbl, bt5h, bt5l, ol_b2, nullptr,
                                          out_final, nullptr, nullptr, GG, FT / 2, SP512, 0, 0, 0);
    }
}

// round 15
// speedup vs baseline: 1.0552x; 1.0337x over previous
#include <cuda_runtime.h>
#include <cuda_bf16.h>
#include <math.h>
#include <stdint.h>

#define NN 100000
#define EE 200000
#define GG 2000
#define DD 300
#define D2 600
#define LL 5
#define FT 512
#define MAXDEG 4
#define BN_EPS 1e-5f

#define SP300 152
#define SP600 304
#define SP512 256

// ---------------- scratch (device globals; no allocation) ----------------
__device__ float d_h[NN * DD];
__device__ int   d_counts[NN];
__device__ int   d_cursor[NN];
__device__ int   d_rowptr[NN + 1];
__device__ int   d_part[NN];
__device__ int   d_bsum[128];
__device__ int   d_eidx[EE];
__device__ int   d_gstart[GG + 1];
__device__ float d_stats[2 * DD];
__device__ float d_mu[DD];
__device__ float d_istd[DD];
__device__ float d_ginv[DD];
__device__ float d_gcoef[DD];
__device__ uint32_t d_aggh[NN * SP300], d_aggl[NN * SP300];
__device__ uint32_t d_hidh[NN * SP600], d_hidl[NN * SP600];
__device__ uint32_t d_hgh[GG * SP300],  d_hgl[GG * SP300];
__device__ uint32_t d_hfh[GG * SP512],  d_hfl[GG * SP512];
__device__ uint32_t d_tbh[GG * SP512],  d_tbl[GG * SP512];
__device__ uint32_t d_bt0h[DD * SP300],          d_bt0l[DD * SP300];
__device__ uint32_t d_bt1h[LL * D2 * SP300],     d_bt1l[LL * D2 * SP300];
__device__ uint32_t d_bt2h[LL * DD * SP600],     d_bt2l[LL * DD * SP600];
__device__ uint32_t d_bt3h[FT * SP300],          d_bt3l[FT * SP300];
__device__ uint32_t d_bt4h[FT * SP512],          d_bt4l[FT * SP512];
__device__ uint32_t d_bt5h[(FT / 2) * SP512],    d_bt5l[(FT / 2) * SP512];

// ---------------- helpers ----------------
__device__ __forceinline__ uint32_t smem_u32(const void* p) {
    uint32_t a;
    asm("{ .reg .u64 t; cvta.to.shared.u64 t, %1; cvt.u32.u64 %0, t; }" : "=r"(a) : "l"(p));
    return a;
}
__device__ __forceinline__ void cp16(uint32_t dst, const void* src, int valid) {
    int sz = valid ? 16 : 0;
    asm volatile("cp.async.cg.shared.global [%0], [%1], 16, %2;" :: "r"(dst), "l"(src), "r"(sz) : "memory");
}
#define CP_COMMIT() asm volatile("cp.async.commit_group;" ::: "memory")
#define CP_WAIT(n)  asm volatile("cp.async.wait_group %0;" :: "n"(n) : "memory")

__device__ __forceinline__ void split2(float x0, float x1, uint32_t& hi, uint32_t& lo) {
    asm("cvt.rn.bf16x2.f32 %0, %1, %2;" : "=r"(hi) : "f"(x1), "f"(x0));
    float h0 = __uint_as_float(hi << 16);
    float h1 = __uint_as_float(hi & 0xFFFF0000u);
    float l0 = x0 - h0, l1 = x1 - h1;
    asm("cvt.rn.bf16x2.f32 %0, %1, %2;" : "=r"(lo) : "f"(l1), "f"(l0));
}
__device__ __forceinline__ void mma_bf16(float* c, const uint32_t* a, const uint32_t* b) {
    asm("mma.sync.aligned.m16n8k16.row.col.f32.bf16.bf16.f32 "
        "{%0,%1,%2,%3}, {%4,%5,%6,%7}, {%8,%9}, {%0,%1,%2,%3};"
        : "+f"(c[0]), "+f"(c[1]), "+f"(c[2]), "+f"(c[3])
        : "r"(a[0]), "r"(a[1]), "r"(a[2]), "r"(a[3]), "r"(b[0]), "r"(b[1]));
}

#define SS 12

// ================ GEMM variant A: 256 threads, BM=128 x BN=128 (round-10 best) ================
#define SM_CH 1536
#define G_STAGES 3
#define GEMM128_SMEM (G_STAGES * 4 * SM_CH * 4)   // 73728 B

__global__ __launch_bounds__(256, 2) void gemm128_k(
    const uint32_t* __restrict__ Ah, const uint32_t* __restrict__ Al,
    const uint32_t* __restrict__ Bh, const uint32_t* __restrict__ Bl,
    const float* __restrict__ bias, const float* __restrict__ add,
    float* __restrict__ C, uint32_t* __restrict__ Oh, uint32_t* __restrict__ Ol,
    int M, int Nc, int SP, int SPo, int relu, int has_add) {
    extern __shared__ uint32_t sm[];
    int tid = threadIdx.x, lane = tid & 31, wid = tid >> 5;
    int wm = wid & 1, wn = wid >> 1;
    int bnc = blockIdx.x * 128;
    int bm = blockIdx.y * 128;
    int nch = SP >> 3;

    float acc[4][4][4];
#pragma unroll
    for (int i = 0; i < 4; i++)
#pragma unroll
        for (int j = 0; j < 4; j++)
#pragma unroll
            for (int r = 0; r < 4; r++) acc[i][j][r] = 0.f;

    int lr = tid >> 1, lg = tid & 1;
    auto load_chunk = [&](int c, int s) {
        uint32_t* base = sm + s * 4 * SM_CH;
        int gu = c * 8 + lg * 4;
        int gr = bm + lr, br = bnc + lr;
        uint32_t off = smem_u32(base + lr * SS + lg * 4);
        int va = gr < M, vb = br < Nc;
        cp16(off,                 Ah + (size_t)gr * SP + gu, va);
        cp16(off + SM_CH * 4,     Al + (size_t)gr * SP + gu, va);
        cp16(off + 2 * SM_CH * 4, Bh + (size_t)br * SP + gu, vb);
        cp16(off + 3 * SM_CH * 4, Bl + (size_t)br * SP + gu, vb);
    };

    load_chunk(0, 0);
    CP_COMMIT();
    if (1 < nch) load_chunk(1, 1);
    CP_COMMIT();

    int row = lane >> 2, qc = lane & 3;
    for (int c = 0; c < nch; c++) {
        CP_WAIT(1);
        __syncthreads();
        {
            int n2 = c + 2;
            if (n2 < nch) load_chunk(n2, n2 % G_STAGES);
            CP_COMMIT();
        }
        uint32_t* base = sm + (c % G_STAGES) * 4 * SM_CH;
        uint32_t* sAh = base;
        uint32_t* sAl = base + SM_CH;
        uint32_t* sBh = base + 2 * SM_CH;
        uint32_t* sBl = base + 3 * SM_CH;
        uint32_t bfh[4][2], bfl[4][2];
#pragma unroll
        for (int nt = 0; nt < 4; nt++) {
            int n = wn * 32 + nt * 8 + row;
            bfh[nt][0] = sBh[n * SS + qc];
            bfh[nt][1] = sBh[n * SS + 4 + qc];
            bfl[nt][0] = sBl[n * SS + qc];
            bfl[nt][1] = sBl[n * SS + 4 + qc];
        }
#pragma unroll
        for (int mt = 0; mt < 4; mt++) {
            int r0 = wm * 64 + mt * 16 + row;
            uint32_t ah[4], al[4];
            ah[0] = sAh[r0 * SS + qc];       ah[1] = sAh[(r0 + 8) * SS + qc];
            ah[2] = sAh[r0 * SS + 4 + qc];   ah[3] = sAh[(r0 + 8) * SS + 4 + qc];
            al[0] = sAl[r0 * SS + qc];       al[1] = sAl[(r0 + 8) * SS + qc];
            al[2] = sAl[r0 * SS + 4 + qc];   al[3] = sAl[(r0 + 8) * SS + 4 + qc];
#pragma unroll
            for (int nt = 0; nt < 4; nt++) mma_bf16(acc[mt][nt], ah, bfl[nt]);
#pragma unroll
            for (int nt = 0; nt < 4; nt++) mma_bf16(acc[mt][nt], al, bfh[nt]);
#pragma unroll
            for (int nt = 0; nt < 4; nt++) mma_bf16(acc[mt][nt], ah, bfh[nt]);
        }
    }

#pragma unroll
    for (int mt = 0; mt < 4; mt++) {
#pragma unroll
        for (int nt = 0; nt < 4; nt++) {
#pragma unroll
            for (int half = 0; half < 2; half++) {
                int gr = bm + wm * 64 + mt * 16 + row + half * 8;
                if (gr >= M) continue;
                int gc0 = bnc + wn * 32 + nt * 8 + qc * 2;
                if (gc0 >= Nc) continue;
                float v0 = acc[mt][nt][half * 2 + 0] + bias[gc0];
                float v1 = acc[mt][nt][half * 2 + 1] + bias[gc0 + 1];
                if (has_add) {
                    v0 += add[(size_t)gr * Nc + gc0];
                    v1 += add[(size_t)gr * Nc + gc0 + 1];
                }
                if (relu) { v0 = fmaxf(v0, 0.f); v1 = fmaxf(v1, 0.f); }
                if (C) {
                    C[(size_t)gr * Nc + gc0] = v0;
                    C[(size_t)gr * Nc + gc0 + 1] = v1;
                }
                if (Oh) {
                    uint32_t hi, lo;
                    split2(v0, v1, hi, lo);
                    int p = gc0 >> 1;
                    Oh[(size_t)gr * SPo + p] = hi;
                    Ol[(size_t)gr * SPo + p] = lo;
                }
            }
        }
    }
}

// ================ GEMM variant B: 128 threads, BM=128 x BN=64 (round-14, for Nc=300) ================
#define A_CH 1536
#define B_CH 768
#define ST_CH (2 * A_CH + 2 * B_CH)
#define GEMM64_SMEM (G_STAGES * ST_CH * 4)   // 55296 B

__global__ __launch_bounds__(128, 4) void gemm64_k(
    const uint32_t* __restrict__ Ah, const uint32_t* __restrict__ Al,
    const uint32_t* __restrict__ Bh, const uint32_t* __restrict__ Bl,
    const float* __restrict__ bias, const float* __restrict__ add,
    float* __restrict__ C, uint32_t* __restrict__ Oh, uint32_t* __restrict__ Ol,
    int M, int Nc, int SP, int SPo, int relu, int has_add) {
    extern __shared__ uint32_t sm[];
    int tid = threadIdx.x, lane = tid & 31, wid = tid >> 5;
    int wm = wid & 1, wn = wid >> 1;
    int bnc = blockIdx.x * 64;
    int bm = blockIdx.y * 128;
    int nch = SP >> 3;

    float acc[4][4][4];
#pragma unroll
    for (int i = 0; i < 4; i++)
#pragma unroll
        for (int j = 0; j < 4; j++)
#pragma unroll
            for (int r = 0; r < 4; r++) acc[i][j][r] = 0.f;

    auto load_chunk = [&](int c, int s) {
        uint32_t* base = sm + s * ST_CH;
        int gu = c * 8;
#pragma unroll
        for (int it = 0; it < 2; it++) {
            int i = tid + it * 128;
            int r = i >> 1, g = i & 1;
            int gr = bm + r;
            uint32_t off = smem_u32(base + r * SS + g * 4);
            int va = gr < M;
            cp16(off,            Ah + (size_t)gr * SP + gu + g * 4, va);
            cp16(off + A_CH * 4, Al + (size_t)gr * SP + gu + g * 4, va);
        }
        {
            int r = tid >> 1, g = tid & 1;
            int br = bnc + r;
            uint32_t off = smem_u32(base + 2 * A_CH + r * SS + g * 4);
            int vb = br < Nc;
            cp16(off,            Bh + (size_t)br * SP + gu + g * 4, vb);
            cp16(off + B_CH * 4, Bl + (size_t)br * SP + gu + g * 4, vb);
        }
    };

    load_chunk(0, 0);
    CP_COMMIT();
    if (1 < nch) load_chunk(1, 1);
    CP_COMMIT();

    int row = lane >> 2, qc = lane & 3;
    for (int c = 0; c < nch; c++) {
        CP_WAIT(1);
        __syncthreads();
        {
            int n2 = c + 2;
            if (n2 < nch) load_chunk(n2, n2 % G_STAGES);
            CP_COMMIT();
        }
        uint32_t* base = sm + (c % G_STAGES) * ST_CH;
        uint32_t* sAh = base;
        uint32_t* sAl = base + A_CH;
        uint32_t* sBh = base + 2 * A_CH;
        uint32_t* sBl = base + 2 * A_CH + B_CH;
        uint32_t bfh[4][2], bfl[4][2];
#pragma unroll
        for (int nt = 0; nt < 4; nt++) {
            int n = wn * 32 + nt * 8 + row;
            bfh[nt][0] = sBh[n * SS + qc];
            bfh[nt][1] = sBh[n * SS + 4 + qc];
            bfl[nt][0] = sBl[n * SS + qc];
            bfl[nt][1] = sBl[n * SS + 4 + qc];
        }
#pragma unroll
        for (int mt = 0; mt < 4; mt++) {
            int r0 = wm * 64 + mt * 16 + row;
            uint32_t ah[4], al[4];
            ah[0] = sAh[r0 * SS + qc];       ah[1] = sAh[(r0 + 8) * SS + qc];
            ah[2] = sAh[r0 * SS + 4 + qc];   ah[3] = sAh[(r0 + 8) * SS + 4 + qc];
            al[0] = sAl[r0 * SS + qc];       al[1] = sAl[(r0 + 8) * SS + qc];
            al[2] = sAl[r0 * SS + 4 + qc];   al[3] = sAl[(r0 + 8) * SS + 4 + qc];
#pragma unroll
            for (int nt = 0; nt < 4; nt++) mma_bf16(acc[mt][nt], ah, bfl[nt]);
#pragma unroll
            for (int nt = 0; nt < 4; nt++) mma_bf16(acc[mt][nt], al, bfh[nt]);
#pragma unroll
            for (int nt = 0; nt < 4; nt++) mma_bf16(acc[mt][nt], ah, bfh[nt]);
        }
    }

#pragma unroll
    for (int mt = 0; mt < 4; mt++) {
#pragma unroll
        for (int nt = 0; nt < 4; nt++) {
#pragma unroll
            for (int half = 0; half < 2; half++) {
                int gr = bm + wm * 64 + mt * 16 + row + half * 8;
                if (gr >= M) continue;
                int gc0 = bnc + wn * 32 + nt * 8 + qc * 2;
                if (gc0 >= Nc) continue;
                float v0 = acc[mt][nt][half * 2 + 0] + bias[gc0];
                float v1 = acc[mt][nt][half * 2 + 1] + bias[gc0 + 1];
                if (has_add) {
                    v0 += add[(size_t)gr * Nc + gc0];
                    v1 += add[(size_t)gr * Nc + gc0 + 1];
                }
                if (relu) { v0 = fmaxf(v0, 0.f); v1 = fmaxf(v1, 0.f); }
                if (C) {
                    C[(size_t)gr * Nc + gc0] = v0;
                    C[(size_t)gr * Nc + gc0 + 1] = v1;
                }
                if (Oh) {
                    uint32_t hi, lo;
                    split2(v0, v1, hi, lo);
                    int p = gc0 >> 1;
                    Oh[(size_t)gr * SPo + p] = hi;
                    Ol[(size_t)gr * SPo + p] = lo;
                }
            }
        }
    }
}

// ---------------- fused weight prep ----------------
struct PrepSeg { const float* w; uint32_t* oh; uint32_t* ol; int K, N, SP; };
struct PrepArgs { PrepSeg s[14]; };

__global__ void prep_all_k(PrepArgs a) {
    PrepSeg p = a.s[blockIdx.y];
    int idx = blockIdx.x * blockDim.x + threadIdx.x;
    if (idx >= p.N * p.SP) return;
    int n = idx / p.SP, ku = idx % p.SP;
    int k0 = ku * 2, k1 = k0 + 1;
    float x0 = (k0 < p.K) ? p.w[(size_t)k0 * p.N + n] : 0.f;
    float x1 = (k1 < p.K) ? p.w[(size_t)k1 * p.N + n] : 0.f;
    uint32_t hi, lo;
    split2(x0, x1, hi, lo);
    p.oh[idx] = hi;
    p.ol[idx] = lo;
}

// ---------------- misc ----------------
__global__ void zero_i(int* p, int n) {
    int i = blockIdx.x * blockDim.x + threadIdx.x;
    if (i < n) p[i] = 0;
}
__global__ void count_k(const int* __restrict__ dst, int* counts) {
    int e = blockIdx.x * blockDim.x + threadIdx.x;
    if (e < EE) atomicAdd(&counts[dst[e]], 1);
}

// ---------------- CSR build ----------------
__global__ void scan1_k(const int* __restrict__ counts, int* part, int* bsum) {
    __shared__ int sh[1024];
    int tid = threadIdx.x;
    int i = blockIdx.x * 1024 + tid;
    int v = (i < NN) ? counts[i] : 0;
    sh[tid] = v;
    __syncthreads();
#pragma unroll
    for (int off = 1; off < 1024; off <<= 1) {
        int t = (tid >= off) ? sh[tid - off] : 0;
        __syncthreads();
        sh[tid] += t;
        __syncthreads();
    }
    if (i < NN) part[i] = sh[tid] - v;
    if (tid == 1023) bsum[blockIdx.x] = sh[1023];
}
__global__ void scan2_k(int* bsum, int nb) {
    if (threadIdx.x == 0 && blockIdx.x == 0) {
        int run = 0;
        for (int b = 0; b < nb; b++) { int t = bsum[b]; bsum[b] = run; run += t; }
    }
}
__global__ void scan3_k(const int* __restrict__ part, const int* __restrict__ bsum, int* rowptr) {
    int i = blockIdx.x * blockDim.x + threadIdx.x;
    if (i < NN) rowptr[i] = part[i] + bsum[i >> 10];
    if (i == 0) rowptr[NN] = EE;
}
__global__ void fill_k(const int* __restrict__ dst, const int* __restrict__ rowptr,
                       int* cursor, int* eidx) {
    int e = blockIdx.x * blockDim.x + threadIdx.x;
    if (e >= EE) return;
    int d = dst[e];
    int pos = atomicAdd(&cursor[d], 1);
    eidx[rowptr[d] + pos] = e;
}

// ---------------- gaussian basis: adds into h ----------------
__global__ void gauss_pre_k(const float* __restrict__ g_stds, float* ginv, float* gcoef) {
    int d = blockIdx.x * blockDim.x + threadIdx.x;
    if (d < DD) {
        float s = fabsf(g_stds[d]) + 0.01f;
        float a = sqrtf(2.0f * 3.14159f);
        ginv[d] = 1.f / s;
        gcoef[d] = 1.f / (a * s);
    }
}
__global__ void gauss_csr_k(const float* __restrict__ dist, const int* __restrict__ rowptr,
                            const int* __restrict__ eidx,
                            const float* __restrict__ g_means,
                            const float* __restrict__ ginv, const float* __restrict__ gcoef,
                            const float* __restrict__ scale_param, float* __restrict__ h) {
    int n = (blockIdx.x * blockDim.x + threadIdx.x) >> 5;
    int lane = threadIdx.x & 31;
    if (n >= NN) return;
    int beg = rowptr[n], end = rowptr[n + 1];
    int degc = min(max(end - beg - 1, 0), MAXDEG - 1);
    float gm[10], gi[10], gc[10], acc[10];
#pragma unroll
    for (int c = 0; c < 10; c++) {
        int d = c * 32 + lane;
        acc[c] = 0.f;
        if (d < DD) { gm[c] = g_means[d]; gi[c] = ginv[d]; gc[c] = gcoef[d]; }
    }
    for (int j = beg; j < end; j++) {
        float de = dist[eidx[j]];
#pragma unroll
        for (int c = 0; c < 10; c++) {
            int d = c * 32 + lane;
            if (d < DD) {
                float z = (de - gm[c]) * gi[c];
                acc[c] += __expf(-0.5f * z * z) * gc[c];
            }
        }
    }
    const float* sp = scale_param + degc * DD;
#pragma unroll
    for (int c = 0; c < 10; c++) {
        int d = c * 32 + lane;
        if (d < DD) h[(size_t)n * DD + d] += acc[c] * expf(sp[d]);
    }
}

// ---------------- attention fusion -> split "fused" ----------------
__global__ void attn_k(const int* __restrict__ x, const float* __restrict__ atom_emb,
                       const float* __restrict__ att_vec,
                       uint32_t* __restrict__ fh, uint32_t* __restrict__ fl) {
    int warp = (blockIdx.x * blockDim.x + threadIdx.x) >> 5;
    int lane = threadIdx.x & 31;
    if (warp >= NN) return;
    const int* xn = x + warp * 9;
    const float2* emb2 = (const float2*)atom_emb;
    const float2* av2 = (const float2*)att_vec;
    int ids[9];
#pragma unroll
    for (int f = 0; f < 9; f++) ids[f] = (f * 119 + xn[f]) * 150;
    float sc[9];
#pragma unroll
    for (int f = 0; f < 9; f++) {
        float p = 0.f;
        for (int pc = lane; pc < 150; pc += 32) {
            float2 e = emb2[ids[f] + pc];
            float2 a = av2[pc];
            p += e.x * a.x + e.y * a.y;
        }
#pragma unroll
        for (int o = 16; o > 0; o >>= 1) p += __shfl_xor_sync(0xffffffffu, p, o);
        sc[f] = p;
    }
    float m = sc[0];
#pragma unroll
    for (int f = 1; f < 9; f++) m = fmaxf(m, sc[f]);
    float s = 0.f;
#pragma unroll
    for (int f = 0; f < 9; f++) { sc[f] = __expf(sc[f] - m); s += sc[f]; }
    float inv = 1.f / s;
    for (int pc = lane; pc < 150; pc += 32) {
        float2 a = make_float2(0.f, 0.f);
#pragma unroll
        for (int f = 0; f < 9; f++) {
            float2 e = emb2[ids[f] + pc];
            a.x += sc[f] * e.x;
            a.y += sc[f] * e.y;
        }
        uint32_t hi, lo;
        split2(a.x * inv, a.y * inv, hi, lo);
        fh[(size_t)warp * SP300 + pc] = hi;
        fl[(size_t)warp * SP300 + pc] = lo;
    }
}

// ---------------- CSR aggregation with inline BN(+relu) ----------------
__global__ void gather_k(const float* __restrict__ h,
                         const int* __restrict__ rowptr, const int* __restrict__ eidx,
                         const int* __restrict__ src, const int* __restrict__ attr,
                         const float* __restrict__ E0, const float* __restrict__ E1,
                         const float* __restrict__ E2,
                         const float* __restrict__ mu, const float* __restrict__ istd,
                         const float* __restrict__ gamma, const float* __restrict__ beta,
                         int apply_bn,
                         uint32_t* __restrict__ aggh, uint32_t* __restrict__ aggl) {
    int n = (blockIdx.x * blockDim.x + threadIdx.x) >> 5;
    int lane = threadIdx.x & 31;
    if (n >= NN) return;
    int beg = rowptr[n], end = rowptr[n + 1];
    const float2* h2 = (const float2*)h;
    const float2* e02 = (const float2*)(E0 + 4 * DD);
    const float2* e12 = (const float2*)E1;
    const float2* e22 = (const float2*)E2;

    float2 scv[5], shv[5];
#pragma unroll
    for (int c = 0; c < 5; c++) {
        int pc = c * 32 + lane;
        if (pc < 150 && apply_bn) {
            float2 g = ((const float2*)gamma)[pc];
            float2 b = ((const float2*)beta)[pc];
            float2 m = ((const float2*)mu)[pc];
            float2 is = ((const float2*)istd)[pc];
            scv[c].x = g.x * is.x; scv[c].y = g.y * is.y;
            shv[c].x = b.x - m.x * scv[c].x; shv[c].y = b.y - m.y * scv[c].y;
        }
    }

    float2 acc[5];
#pragma unroll
    for (int c = 0; c < 5; c++) {
        int pc = c * 32 + lane;
        if (pc < 150) {
            float2 v = h2[(size_t)n * 150 + pc];
            if (apply_bn) {
                v.x = fmaxf(v.x * scv[c].x + shv[c].x, 0.f);
                v.y = fmaxf(v.y * scv[c].y + shv[c].y, 0.f);
            }
            float2 s0 = e02[pc], s1 = e12[pc], s2 = e22[pc];
            acc[c].x = v.x + s0.x + s1.x + s2.x;
            acc[c].y = v.y + s0.y + s1.y + s2.y;
        }
    }
    for (int j = beg; j < end; j++) {
        int e = eidx[j];
        int s = src[e];
        int a0 = attr[e * 3 + 0], a1 = attr[e * 3 + 1], a2 = attr[e * 3 + 2];
        const float2* hs = h2 + (size_t)s * 150;
        const float2* p0 = (const float2*)(E0 + a0 * DD);
        const float2* p1 = (const float2*)(E1 + a1 * DD);
        const float2* p2 = (const float2*)(E2 + a2 * DD);
#pragma unroll
        for (int c = 0; c < 5; c++) {
            int pc = c * 32 + lane;
            if (pc < 150) {
                float2 v = hs[pc];
                if (apply_bn) {
                    v.x = fmaxf(v.x * scv[c].x + shv[c].x, 0.f);
                    v.y = fmaxf(v.y * scv[c].y + shv[c].y, 0.f);
                }
                float2 q0 = p0[pc], q1 = p1[pc], q2 = p2[pc];
                acc[c].x += v.x + q0.x + q1.x + q2.x;
                acc[c].y += v.y + q0.y + q1.y + q2.y;
            }
        }
    }
#pragma unroll
    for (int c = 0; c < 5; c++) {
        int pc = c * 32 + lane;
        if (pc < 150) {
            uint32_t hi, lo;
            split2(acc[c].x, acc[c].y, hi, lo);
            aggh[(size_t)n * SP300 + pc] = hi;
            aggl[(size_t)n * SP300 + pc] = lo;
        }
    }
}

// ---------------- batchnorm ----------------
#define BN_RPB 128
__global__ void bn_stats_k(const float* __restrict__ h, float* stats) {
    int row0 = blockIdx.x * BN_RPB;
    int rend = min(row0 + BN_RPB, NN);
    int c0 = threadIdx.x;
    int c1 = threadIdx.x + 256;
    float s0 = 0.f, q0 = 0.f, s1 = 0.f, q1 = 0.f;
    for (int r = row0; r < rend; r++) {
        float v0 = h[(size_t)r * DD + c0];
        s0 += v0; q0 += v0 * v0;
        if (c1 < DD) {
            float v1 = h[(size_t)r * DD + c1];
            s1 += v1; q1 += v1 * v1;
        }
    }
    atomicAdd(&stats[c0], s0);
    atomicAdd(&stats[DD + c0], q0);
    if (c1 < DD) {
        atomicAdd(&stats[c1], s1);
        atomicAdd(&stats[DD + c1], q1);
    }
}
__global__ void bn_fin_k(const float* __restrict__ stats, float* mu, float* istd, float* stats_z) {
    int d = blockIdx.x * blockDim.x + threadIdx.x;
    if (d < DD) {
        float m = stats[d] / (float)NN;
        float v = stats[DD + d] / (float)NN - m * m;
        v = fmaxf(v, 0.f);
        mu[d] = m;
        istd[d] = rsqrtf(v + BN_EPS);
        stats_z[d] = 0.f;
        stats_z[DD + d] = 0.f;
    }
}

// ---------------- pooling with inline BN (last layer) ----------------
__global__ void gstart_k(const int* __restrict__ batch, int* gstart) {
    int g = blockIdx.x * blockDim.x + threadIdx.x;
    if (g > GG) return;
    int lo = 0, hi = NN;
    while (lo < hi) {
        int mid = (lo + hi) >> 1;
        if (batch[mid] < g) lo = mid + 1; else hi = mid;
    }
    gstart[g] = lo;
}
__global__ void pool_k(const float* __restrict__ h, const int* __restrict__ gstart,
                       const float* __restrict__ mu, const float* __restrict__ istd,
                       const float* __restrict__ gamma, const float* __restrict__ beta,
                       uint32_t* __restrict__ hgh, uint32_t* __restrict__ hgl) {
    int g = blockIdx.x;
    int pc = threadIdx.x;
    if (pc >= 150) return;
    const float2* h2 = (const float2*)h;
    float2 gm = ((const float2*)gamma)[pc];
    float2 bt = ((const float2*)beta)[pc];
    float2 m = ((const float2*)mu)[pc];
    float2 is = ((const float2*)istd)[pc];
    float2 sc, sh;
    sc.x = gm.x * is.x; sc.y = gm.y * is.y;
    sh.x = bt.x - m.x * sc.x; sh.y = bt.y - m.y * sc.y;
    int s = gstart[g], e = gstart[g + 1];
    float2 a = make_float2(0.f, 0.f);
    for (int r = s; r < e; r++) {
        float2 v = h2[(size_t)r * 150 + pc];
        a.x += v.x * sc.x + sh.x;
        a.y += v.y * sc.y + sh.y;
    }
    float inv = 1.f / fmaxf((float)(e - s), 1.f);
    uint32_t hi, lo;
    split2(a.x * inv, a.y * inv, hi, lo);
    hgh[(size_t)g * SP300 + pc] = hi;
    hgl[(size_t)g * SP300 + pc] = lo;
}

// ---------------- host ----------------
static float* symf(const void* sym) { void* p = nullptr; cudaGetSymbolAddress(&p, sym); return (float*)p; }
static int* symi(const void* sym) { void* p = nullptr; cudaGetSymbolAddress(&p, sym); return (int*)p; }
static uint32_t* symu(const void* sym) { void* p = nullptr; cudaGetSymbolAddress(&p, sym); return (uint32_t*)p; }
static inline int cdiv(int a, int b) { return (a + b - 1) / b; }

extern "C" void kernel_launch(void* const* d_in, const int* in_sizes, int n_in,
                              void* d_out, int out_size) {
    const int* x            = (const int*)d_in[0];
    const int* edge_index   = (const int*)d_in[1];
    const int* edge_attr    = (const int*)d_in[2];
    const float* edge_dist  = (const float*)d_in[3];
    const int* batch        = (const int*)d_in[4];
    const float* atom_emb   = (const float*)d_in[5];
    const float* att_vec    = (const float*)d_in[6];
    const float* out_lin_w  = (const float*)d_in[7];
    const float* out_lin_b  = (const float*)d_in[8];
    const float* g_means    = (const float*)d_in[9];
    const float* g_stds     = (const float*)d_in[10];
    const float* scale_par  = (const float*)d_in[11];
    const float* edge_emb   = (const float*)d_in[12];
    const float* mlp_w1     = (const float*)d_in[13];
    const float* mlp_b1     = (const float*)d_in[14];
    const float* mlp_w2     = (const float*)d_in[15];
    const float* mlp_b2     = (const float*)d_in[16];
    const float* bn_gamma   = (const float*)d_in[17];
    const float* bn_beta    = (const float*)d_in[18];
    const float* feat_w     = (const float*)d_in[19];
    const float* feat_b     = (const float*)d_in[20];
    const float* ol_w1      = (const float*)d_in[21];
    const float* ol_b1      = (const float*)d_in[22];
    const float* ol_w2      = (const float*)d_in[23];
    const float* ol_b2      = (const float*)d_in[24];

    const int* e_src = edge_index;
    const int* e_dst = edge_index + EE;

    float* h      = symf(d_h);
    int*   counts = symi(d_counts);
    int*   cursor = symi(d_cursor);
    int*   rowptr = symi(d_rowptr);
    int*   part   = symi(d_part);
    int*   bsum   = symi(d_bsum);
    int*   eidx   = symi(d_eidx);
    int*   gstart = symi(d_gstart);
    float* stats  = symf(d_stats);
    float* mu     = symf(d_mu);
    float* istd   = symf(d_istd);
    float* ginv   = symf(d_ginv);
    float* gcoef  = symf(d_gcoef);
    uint32_t* aggh = symu(d_aggh), *aggl = symu(d_aggl);
    uint32_t* hidh = symu(d_hidh), *hidl = symu(d_hidl);
    uint32_t* hgh = symu(d_hgh), *hgl = symu(d_hgl);
    uint32_t* hfh = symu(d_hfh), *hfl = symu(d_hfl);
    uint32_t* tbh = symu(d_tbh), *tbl = symu(d_tbl);
    uint32_t* bt0h = symu(d_bt0h), *bt0l = symu(d_bt0l);
    uint32_t* bt1h = symu(d_bt1h), *bt1l = symu(d_bt1l);
    uint32_t* bt2h = symu(d_bt2h), *bt2l = symu(d_bt2l);
    uint32_t* bt3h = symu(d_bt3h), *bt3l = symu(d_bt3l);
    uint32_t* bt4h = symu(d_bt4h), *bt4l = symu(d_bt4l);
    uint32_t* bt5h = symu(d_bt5h), *bt5l = symu(d_bt5l);

    float* out_hfeat = (float*)d_out;
    float* out_final = (float*)d_out + GG * FT;

    const int T = 256;
    cudaFuncSetAttribute(gemm128_k, cudaFuncAttributeMaxDynamicSharedMemorySize, GEMM128_SMEM);
    cudaFuncSetAttribute(gemm64_k, cudaFuncAttributeMaxDynamicSharedMemorySize, GEMM64_SMEM);

    // launch 1: fused weight prep
    {
        PrepArgs pa;
        pa.s[0] = { out_lin_w, bt0h, bt0l, DD, DD, SP300 };
        for (int l = 0; l < LL; l++) {
            pa.s[1 + l] = { mlp_w1 + (size_t)l * DD * D2,
                            bt1h + (size_t)l * D2 * SP300, bt1l + (size_t)l * D2 * SP300,
                            DD, D2, SP300 };
            pa.s[6 + l] = { mlp_w2 + (size_t)l * D2 * DD,
                            bt2h + (size_t)l * DD * SP600, bt2l + (size_t)l * DD * SP600,
                            D2, DD, SP600 };
        }
        pa.s[11] = { feat_w, bt3h, bt3l, DD, FT, SP300 };
        pa.s[12] = { ol_w1, bt4h, bt4l, FT, FT, SP512 };
        pa.s[13] = { ol_w2, bt5h, bt5l, FT, FT / 2, SP512 };
        dim3 g(cdiv(FT * SP512, T), 14);
        prep_all_k<<<g, T>>>(pa);
    }
    // launch 2: attention fusion
    attn_k<<<cdiv(NN * 32, T), T>>>(x, atom_emb, att_vec, aggh, aggl);
    // launch 3
    zero_i<<<cdiv(NN, T), T>>>(counts, NN);
    // launch 4 (ncu sample target): layer-0 GEMM, Nc=300 -> BN=64 variant
    {
        dim3 g(cdiv(DD, 64), cdiv(NN, 128));
        gemm64_k<<<g, 128, GEMM64_SMEM>>>(aggh, aggl, bt0h, bt0l, out_lin_b, nullptr,
                                          h, nullptr, nullptr, NN, DD, SP300, 0, 0, 0);
    }
    // CSR build
    count_k<<<cdiv(EE, T), T>>>(e_dst, counts);
    scan1_k<<<cdiv(NN, 1024), 1024>>>(counts, part, bsum);
    scan2_k<<<1, 32>>>(bsum, cdiv(NN, 1024));
    scan3_k<<<cdiv(NN, T), T>>>(part, bsum, rowptr);
    zero_i<<<cdiv(NN, T), T>>>(cursor, NN);
    fill_k<<<cdiv(EE, T), T>>>(e_dst, rowptr, cursor, eidx);
    // gaussian basis adds into h
    gauss_pre_k<<<cdiv(DD, T), T>>>(g_stds, ginv, gcoef);
    gauss_csr_k<<<cdiv(NN * 32, T), T>>>(edge_dist, rowptr, eidx, g_means, ginv, gcoef,
                                         scale_par, h);

    // --- L layers ---
    for (int l = 0; l < LL; l++) {
        const float* E0 = edge_emb + (size_t)(l * 3 + 0) * 5 * DD;
        const float* E1 = edge_emb + (size_t)(l * 3 + 1) * 5 * DD;
        const float* E2 = edge_emb + (size_t)(l * 3 + 2) * 5 * DD;
        gather_k<<<cdiv(NN * 32, T), T>>>(h, rowptr, eidx, e_src, edge_attr, E0, E1, E2,
                                          mu, istd, bn_gamma + (l - 1) * DD, bn_beta + (l - 1) * DD,
                                          (l > 0) ? 1 : 0, aggh, aggl);
        {
            // w1: Nc=600 -> BN=128 variant
            dim3 g1(cdiv(D2, 128), cdiv(NN, 128));
            gemm128_k<<<g1, 256, GEMM128_SMEM>>>(aggh, aggl,
                                                 bt1h + (size_t)l * D2 * SP300,
                                                 bt1l + (size_t)l * D2 * SP300,
                                                 mlp_b1 + l * D2, nullptr,
                                                 nullptr, hidh, hidl, NN, D2, SP300, SP600, 1, 0);
            // w2: Nc=300 -> BN=64 variant
            dim3 g2(cdiv(DD, 64), cdiv(NN, 128));
            gemm64_k<<<g2, 128, GEMM64_SMEM>>>(hidh, hidl,
                                               bt2h + (size_t)l * DD * SP600,
                                               bt2l + (size_t)l * DD * SP600,
                                               mlp_b2 + l * DD, nullptr,
                                               h, nullptr, nullptr, NN, DD, SP600, 0, 0, 0);
        }
        bn_stats_k<<<cdiv(NN, BN_RPB), 256>>>(h, stats);
        bn_fin_k<<<cdiv(DD, T), T>>>(stats, mu, istd, stats);
    }

    // --- pooling with inline BN of last layer ---
    gstart_k<<<cdiv(GG + 1, T), T>>>(batch, gstart);
    pool_k<<<GG, 160>>>(h, gstart, mu, istd, bn_gamma + (LL - 1) * DD, bn_beta + (LL - 1) * DD,
                        hgh, hgl);

    // --- head (all Nc multiples of 128 or close -> BN=128 variant) ---
    {
        dim3 g(cdiv(FT, 128), cdiv(GG, 128));
        gemm128_k<<<g, 256, GEMM128_SMEM>>>(hgh, hgl, bt3h, bt3l, feat_b, nullptr,
                                            out_hfeat, hfh, hfl, GG, FT, SP300, SP512, 0, 0);
    }
    {
        dim3 g(cdiv(FT, 128), cdiv(GG, 128));
        gemm128_k<<<g, 256, GEMM128_SMEM>>>(hfh, hfl, bt4h, bt4l, ol_b1, nullptr,
                                            nullptr, tbh, tbl, GG, FT, SP512, SP512, 1, 0);
    }
    {
        dim3 g(cdiv(FT / 2, 128), cdiv(GG, 128));
        gemm128_k<<<g, 256, GEMM128_SMEM>>>(tbh, tbl, bt5h, bt5l, ol_b2, nullptr,
                                            out_final, nullptr, nullptr, GG, FT / 2, SP512, 0, 0, 0);
    }
}

// round 16
// speedup vs baseline: 1.0912x; 1.0341x over previous
#include <cuda_runtime.h>
#include <cuda_bf16.h>
#include <math.h>
#include <stdint.h>

#define NN 100000
#define EE 200000
#define GG 2000
#define DD 300
#define D2 600
#define LL 5
#define FT 512
#define MAXDEG 4
#define BN_EPS 1e-5f

#define SP300 152
#define SP600 304
#define SP512 256

// ---------------- scratch (device globals; no allocation) ----------------
__device__ float d_h[NN * DD];
__device__ int   d_counts[NN];
__device__ int   d_cursor[NN];
__device__ int   d_rowptr[NN + 1];
__device__ int   d_part[NN];
__device__ int   d_bsum[128];
__device__ int   d_eidx[EE];
__device__ int   d_gstart[GG + 1];
__device__ float d_stats[2 * DD];
__device__ float d_mu[DD];
__device__ float d_istd[DD];
__device__ float d_ginv[DD];
__device__ float d_gcoef[DD];
__device__ uint32_t d_aggh[NN * SP300], d_aggl[NN * SP300];
__device__ uint32_t d_hidh[NN * SP600], d_hidl[NN * SP600];
__device__ uint32_t d_hgh[GG * SP300],  d_hgl[GG * SP300];
__device__ uint32_t d_hfh[GG * SP512],  d_hfl[GG * SP512];
__device__ uint32_t d_tbh[GG * SP512],  d_tbl[GG * SP512];
__device__ uint32_t d_bt0h[DD * SP300],          d_bt0l[DD * SP300];
__device__ uint32_t d_bt1h[LL * D2 * SP300],     d_bt1l[LL * D2 * SP300];
__device__ uint32_t d_bt2h[LL * DD * SP600],     d_bt2l[LL * DD * SP600];
__device__ uint32_t d_bt3h[FT * SP300],          d_bt3l[FT * SP300];
__device__ uint32_t d_bt4h[FT * SP512],          d_bt4l[FT * SP512];
__device__ uint32_t d_bt5h[(FT / 2) * SP512],    d_bt5l[(FT / 2) * SP512];

// ---------------- helpers ----------------
__device__ __forceinline__ uint32_t smem_u32(const void* p) {
    uint32_t a;
    asm("{ .reg .u64 t; cvta.to.shared.u64 t, %1; cvt.u32.u64 %0, t; }" : "=r"(a) : "l"(p));
    return a;
}
__device__ __forceinline__ void cp16(uint32_t dst, const void* src, int valid) {
    int sz = valid ? 16 : 0;
    asm volatile("cp.async.cg.shared.global [%0], [%1], 16, %2;" :: "r"(dst), "l"(src), "r"(sz) : "memory");
}
#define CP_COMMIT() asm volatile("cp.async.commit_group;" ::: "memory")
#define CP_WAIT(n)  asm volatile("cp.async.wait_group %0;" :: "n"(n) : "memory")

__device__ __forceinline__ void split2(float x0, float x1, uint32_t& hi, uint32_t& lo) {
    asm("cvt.rn.bf16x2.f32 %0, %1, %2;" : "=r"(hi) : "f"(x1), "f"(x0));
    float h0 = __uint_as_float(hi << 16);
    float h1 = __uint_as_float(hi & 0xFFFF0000u);
    float l0 = x0 - h0, l1 = x1 - h1;
    asm("cvt.rn.bf16x2.f32 %0, %1, %2;" : "=r"(lo) : "f"(l1), "f"(l0));
}
__device__ __forceinline__ void mma_bf16(float* c, const uint32_t* a, const uint32_t* b) {
    asm("mma.sync.aligned.m16n8k16.row.col.f32.bf16.bf16.f32 "
        "{%0,%1,%2,%3}, {%4,%5,%6,%7}, {%8,%9}, {%0,%1,%2,%3};"
        : "+f"(c[0]), "+f"(c[1]), "+f"(c[2]), "+f"(c[3])
        : "r"(a[0]), "r"(a[1]), "r"(a[2]), "r"(a[3]), "r"(b[0]), "r"(b[1]));
}
__device__ __forceinline__ void ldsm4(uint32_t& r0, uint32_t& r1, uint32_t& r2, uint32_t& r3,
                                      uint32_t addr) {
    asm volatile("ldmatrix.sync.aligned.m8n8.x4.shared.b16 {%0,%1,%2,%3}, [%4];"
                 : "=r"(r0), "=r"(r1), "=r"(r2), "=r"(r3) : "r"(addr));
}

#define SS 12

// ================ GEMM variant A: 256 threads, BM=128 x BN=128 (round-10 best; plain LDS) ================
#define SM_CH 1536
#define G_STAGES 3
#define GEMM128_SMEM (G_STAGES * 4 * SM_CH * 4)   // 73728 B

__global__ __launch_bounds__(256, 2) void gemm128_k(
    const uint32_t* __restrict__ Ah, const uint32_t* __restrict__ Al,
    const uint32_t* __restrict__ Bh, const uint32_t* __restrict__ Bl,
    const float* __restrict__ bias, const float* __restrict__ add,
    float* __restrict__ C, uint32_t* __restrict__ Oh, uint32_t* __restrict__ Ol,
    int M, int Nc, int SP, int SPo, int relu, int has_add) {
    extern __shared__ uint32_t sm[];
    int tid = threadIdx.x, lane = tid & 31, wid = tid >> 5;
    int wm = wid & 1, wn = wid >> 1;
    int bnc = blockIdx.x * 128;
    int bm = blockIdx.y * 128;
    int nch = SP >> 3;

    float acc[4][4][4];
#pragma unroll
    for (int i = 0; i < 4; i++)
#pragma unroll
        for (int j = 0; j < 4; j++)
#pragma unroll
            for (int r = 0; r < 4; r++) acc[i][j][r] = 0.f;

    int lr = tid >> 1, lg = tid & 1;
    auto load_chunk = [&](int c, int s) {
        uint32_t* base = sm + s * 4 * SM_CH;
        int gu = c * 8 + lg * 4;
        int gr = bm + lr, br = bnc + lr;
        uint32_t off = smem_u32(base + lr * SS + lg * 4);
        int va = gr < M, vb = br < Nc;
        cp16(off,                 Ah + (size_t)gr * SP + gu, va);
        cp16(off + SM_CH * 4,     Al + (size_t)gr * SP + gu, va);
        cp16(off + 2 * SM_CH * 4, Bh + (size_t)br * SP + gu, vb);
        cp16(off + 3 * SM_CH * 4, Bl + (size_t)br * SP + gu, vb);
    };

    load_chunk(0, 0);
    CP_COMMIT();
    if (1 < nch) load_chunk(1, 1);
    CP_COMMIT();

    int row = lane >> 2, qc = lane & 3;
    for (int c = 0; c < nch; c++) {
        CP_WAIT(1);
        __syncthreads();
        {
            int n2 = c + 2;
            if (n2 < nch) load_chunk(n2, n2 % G_STAGES);
            CP_COMMIT();
        }
        uint32_t* base = sm + (c % G_STAGES) * 4 * SM_CH;
        uint32_t* sAh = base;
        uint32_t* sAl = base + SM_CH;
        uint32_t* sBh = base + 2 * SM_CH;
        uint32_t* sBl = base + 3 * SM_CH;
        uint32_t bfh[4][2], bfl[4][2];
#pragma unroll
        for (int nt = 0; nt < 4; nt++) {
            int n = wn * 32 + nt * 8 + row;
            bfh[nt][0] = sBh[n * SS + qc];
            bfh[nt][1] = sBh[n * SS + 4 + qc];
            bfl[nt][0] = sBl[n * SS + qc];
            bfl[nt][1] = sBl[n * SS + 4 + qc];
        }
#pragma unroll
        for (int mt = 0; mt < 4; mt++) {
            int r0 = wm * 64 + mt * 16 + row;
            uint32_t ah[4], al[4];
            ah[0] = sAh[r0 * SS + qc];       ah[1] = sAh[(r0 + 8) * SS + qc];
            ah[2] = sAh[r0 * SS + 4 + qc];   ah[3] = sAh[(r0 + 8) * SS + 4 + qc];
            al[0] = sAl[r0 * SS + qc];       al[1] = sAl[(r0 + 8) * SS + qc];
            al[2] = sAl[r0 * SS + 4 + qc];   al[3] = sAl[(r0 + 8) * SS + 4 + qc];
#pragma unroll
            for (int nt = 0; nt < 4; nt++) mma_bf16(acc[mt][nt], ah, bfl[nt]);
#pragma unroll
            for (int nt = 0; nt < 4; nt++) mma_bf16(acc[mt][nt], al, bfh[nt]);
#pragma unroll
            for (int nt = 0; nt < 4; nt++) mma_bf16(acc[mt][nt], ah, bfh[nt]);
        }
    }

#pragma unroll
    for (int mt = 0; mt < 4; mt++) {
#pragma unroll
        for (int nt = 0; nt < 4; nt++) {
#pragma unroll
            for (int half = 0; half < 2; half++) {
                int gr = bm + wm * 64 + mt * 16 + row + half * 8;
                if (gr >= M) continue;
                int gc0 = bnc + wn * 32 + nt * 8 + qc * 2;
                if (gc0 >= Nc) continue;
                float v0 = acc[mt][nt][half * 2 + 0] + bias[gc0];
                float v1 = acc[mt][nt][half * 2 + 1] + bias[gc0 + 1];
                if (has_add) {
                    v0 += add[(size_t)gr * Nc + gc0];
                    v1 += add[(size_t)gr * Nc + gc0 + 1];
                }
                if (relu) { v0 = fmaxf(v0, 0.f); v1 = fmaxf(v1, 0.f); }
                if (C) {
                    C[(size_t)gr * Nc + gc0] = v0;
                    C[(size_t)gr * Nc + gc0 + 1] = v1;
                }
                if (Oh) {
                    uint32_t hi, lo;
                    split2(v0, v1, hi, lo);
                    int p = gc0 >> 1;
                    Oh[(size_t)gr * SPo + p] = hi;
                    Ol[(size_t)gr * SPo + p] = lo;
                }
            }
        }
    }
}

// ================ GEMM variant B: 128 threads, BM=128 x BN=64, ldmatrix frags (Nc=300) ================
#define A_CH 1536
#define B_CH 768
#define ST_CH (2 * A_CH + 2 * B_CH)
#define GEMM64_SMEM (G_STAGES * ST_CH * 4)   // 55296 B

__global__ __launch_bounds__(128, 4) void gemm64_k(
    const uint32_t* __restrict__ Ah, const uint32_t* __restrict__ Al,
    const uint32_t* __restrict__ Bh, const uint32_t* __restrict__ Bl,
    const float* __restrict__ bias, const float* __restrict__ add,
    float* __restrict__ C, uint32_t* __restrict__ Oh, uint32_t* __restrict__ Ol,
    int M, int Nc, int SP, int SPo, int relu, int has_add) {
    extern __shared__ uint32_t sm[];
    int tid = threadIdx.x, lane = tid & 31, wid = tid >> 5;
    int wm = wid & 1, wn = wid >> 1;
    int bnc = blockIdx.x * 64;
    int bm = blockIdx.y * 128;
    int nch = SP >> 3;

    float acc[4][4][4];
#pragma unroll
    for (int i = 0; i < 4; i++)
#pragma unroll
        for (int j = 0; j < 4; j++)
#pragma unroll
            for (int r = 0; r < 4; r++) acc[i][j][r] = 0.f;

    auto load_chunk = [&](int c, int s) {
        uint32_t* base = sm + s * ST_CH;
        int gu = c * 8;
#pragma unroll
        for (int it = 0; it < 2; it++) {
            int i = tid + it * 128;
            int r = i >> 1, g = i & 1;
            int gr = bm + r;
            uint32_t off = smem_u32(base + r * SS + g * 4);
            int va = gr < M;
            cp16(off,            Ah + (size_t)gr * SP + gu + g * 4, va);
            cp16(off + A_CH * 4, Al + (size_t)gr * SP + gu + g * 4, va);
        }
        {
            int r = tid >> 1, g = tid & 1;
            int br = bnc + r;
            uint32_t off = smem_u32(base + 2 * A_CH + r * SS + g * 4);
            int vb = br < Nc;
            cp16(off,            Bh + (size_t)br * SP + gu + g * 4, vb);
            cp16(off + B_CH * 4, Bl + (size_t)br * SP + gu + g * 4, vb);
        }
    };

    load_chunk(0, 0);
    CP_COMMIT();
    if (1 < nch) load_chunk(1, 1);
    CP_COMMIT();

    // ldmatrix lane addressing (R8-proven quadrant mapping)
    int g8 = lane >> 3, l8 = lane & 7;
    // A: quadrants = (row+0/+8) x (k-half 0/1)
    uint32_t aOff = (uint32_t)(wm * 64 + ((g8 & 1) << 3) + l8) * (SS * 4) + ((g8 >> 1) << 4);
    // B: quadrants = (n+0/+8) x (k-half 0/1)
    uint32_t bOff = (uint32_t)(wn * 32 + ((g8 >> 1) << 3) + l8) * (SS * 4) + ((g8 & 1) << 4);
    uint32_t smBase = smem_u32(sm);

    int row = lane >> 2, qc = lane & 3;
    for (int c = 0; c < nch; c++) {
        CP_WAIT(1);
        __syncthreads();
        {
            int n2 = c + 2;
            if (n2 < nch) load_chunk(n2, n2 % G_STAGES);
            CP_COMMIT();
        }
        uint32_t chunkBase = smBase + (uint32_t)(c % G_STAGES) * ST_CH * 4;
        uint32_t bfh[4][2], bfl[4][2];
        {
            uint32_t ba = chunkBase + 2 * A_CH * 4 + bOff;
            ldsm4(bfh[0][0], bfh[0][1], bfh[1][0], bfh[1][1], ba);
            ldsm4(bfh[2][0], bfh[2][1], bfh[3][0], bfh[3][1], ba + 16 * SS * 4);
            uint32_t bb = chunkBase + (2 * A_CH + B_CH) * 4 + bOff;
            ldsm4(bfl[0][0], bfl[0][1], bfl[1][0], bfl[1][1], bb);
            ldsm4(bfl[2][0], bfl[2][1], bfl[3][0], bfl[3][1], bb + 16 * SS * 4);
        }
#pragma unroll
        for (int mt = 0; mt < 4; mt++) {
            uint32_t ah[4], al[4];
            uint32_t aa = chunkBase + aOff + (uint32_t)mt * 16 * SS * 4;
            ldsm4(ah[0], ah[1], ah[2], ah[3], aa);
            ldsm4(al[0], al[1], al[2], al[3], aa + A_CH * 4);
#pragma unroll
            for (int nt = 0; nt < 4; nt++) mma_bf16(acc[mt][nt], ah, bfl[nt]);
#pragma unroll
            for (int nt = 0; nt < 4; nt++) mma_bf16(acc[mt][nt], al, bfh[nt]);
#pragma unroll
            for (int nt = 0; nt < 4; nt++) mma_bf16(acc[mt][nt], ah, bfh[nt]);
        }
    }

#pragma unroll
    for (int mt = 0; mt < 4; mt++) {
#pragma unroll
        for (int nt = 0; nt < 4; nt++) {
#pragma unroll
            for (int half = 0; half < 2; half++) {
                int gr = bm + wm * 64 + mt * 16 + row + half * 8;
                if (gr >= M) continue;
                int gc0 = bnc + wn * 32 + nt * 8 + qc * 2;
                if (gc0 >= Nc) continue;
                float v0 = acc[mt][nt][half * 2 + 0] + bias[gc0];
                float v1 = acc[mt][nt][half * 2 + 1] + bias[gc0 + 1];
                if (has_add) {
                    v0 += add[(size_t)gr * Nc + gc0];
                    v1 += add[(size_t)gr * Nc + gc0 + 1];
                }
                if (relu) { v0 = fmaxf(v0, 0.f); v1 = fmaxf(v1, 0.f); }
                if (C) {
                    C[(size_t)gr * Nc + gc0] = v0;
                    C[(size_t)gr * Nc + gc0 + 1] = v1;
                }
                if (Oh) {
                    uint32_t hi, lo;
                    split2(v0, v1, hi, lo);
                    int p = gc0 >> 1;
                    Oh[(size_t)gr * SPo + p] = hi;
                    Ol[(size_t)gr * SPo + p] = lo;
                }
            }
        }
    }
}

// ---------------- fused weight prep ----------------
struct PrepSeg { const float* w; uint32_t* oh; uint32_t* ol; int K, N, SP; };
struct PrepArgs { PrepSeg s[14]; };

__global__ void prep_all_k(PrepArgs a) {
    PrepSeg p = a.s[blockIdx.y];
    int idx = blockIdx.x * blockDim.x + threadIdx.x;
    if (idx >= p.N * p.SP) return;
    int n = idx / p.SP, ku = idx % p.SP;
    int k0 = ku * 2, k1 = k0 + 1;
    float x0 = (k0 < p.K) ? p.w[(size_t)k0 * p.N + n] : 0.f;
    float x1 = (k1 < p.K) ? p.w[(size_t)k1 * p.N + n] : 0.f;
    uint32_t hi, lo;
    split2(x0, x1, hi, lo);
    p.oh[idx] = hi;
    p.ol[idx] = lo;
}

// ---------------- misc ----------------
__global__ void zero_i(int* p, int n) {
    int i = blockIdx.x * blockDim.x + threadIdx.x;
    if (i < n) p[i] = 0;
}
__global__ void count_k(const int* __restrict__ dst, int* counts) {
    int e = blockIdx.x * blockDim.x + threadIdx.x;
    if (e < EE) atomicAdd(&counts[dst[e]], 1);
}

// ---------------- CSR build ----------------
__global__ void scan1_k(const int* __restrict__ counts, int* part, int* bsum) {
    __shared__ int sh[1024];
    int tid = threadIdx.x;
    int i = blockIdx.x * 1024 + tid;
    int v = (i < NN) ? counts[i] : 0;
    sh[tid] = v;
    __syncthreads();
#pragma unroll
    for (int off = 1; off < 1024; off <<= 1) {
        int t = (tid >= off) ? sh[tid - off] : 0;
        __syncthreads();
        sh[tid] += t;
        __syncthreads();
    }
    if (i < NN) part[i] = sh[tid] - v;
    if (tid == 1023) bsum[blockIdx.x] = sh[1023];
}
__global__ void scan2_k(int* bsum, int nb) {
    if (threadIdx.x == 0 && blockIdx.x == 0) {
        int run = 0;
        for (int b = 0; b < nb; b++) { int t = bsum[b]; bsum[b] = run; run += t; }
    }
}
__global__ void scan3_k(const int* __restrict__ part, const int* __restrict__ bsum, int* rowptr) {
    int i = blockIdx.x * blockDim.x + threadIdx.x;
    if (i < NN) rowptr[i] = part[i] + bsum[i >> 10];
    if (i == 0) rowptr[NN] = EE;
}
__global__ void fill_k(const int* __restrict__ dst, const int* __restrict__ rowptr,
                       int* cursor, int* eidx) {
    int e = blockIdx.x * blockDim.x + threadIdx.x;
    if (e >= EE) return;
    int d = dst[e];
    int pos = atomicAdd(&cursor[d], 1);
    eidx[rowptr[d] + pos] = e;
}

// ---------------- gaussian basis: adds into h ----------------
__global__ void gauss_pre_k(const float* __restrict__ g_stds, float* ginv, float* gcoef) {
    int d = blockIdx.x * blockDim.x + threadIdx.x;
    if (d < DD) {
        float s = fabsf(g_stds[d]) + 0.01f;
        float a = sqrtf(2.0f * 3.14159f);
        ginv[d] = 1.f / s;
        gcoef[d] = 1.f / (a * s);
    }
}
__global__ void gauss_csr_k(const float* __restrict__ dist, const int* __restrict__ rowptr,
                            const int* __restrict__ eidx,
                            const float* __restrict__ g_means,
                            const float* __restrict__ ginv, const float* __restrict__ gcoef,
                            const float* __restrict__ scale_param, float* __restrict__ h) {
    int n = (blockIdx.x * blockDim.x + threadIdx.x) >> 5;
    int lane = threadIdx.x & 31;
    if (n >= NN) return;
    int beg = rowptr[n], end = rowptr[n + 1];
    int degc = min(max(end - beg - 1, 0), MAXDEG - 1);
    float gm[10], gi[10], gc[10], acc[10];
#pragma unroll
    for (int c = 0; c < 10; c++) {
        int d = c * 32 + lane;
        acc[c] = 0.f;
        if (d < DD) { gm[c] = g_means[d]; gi[c] = ginv[d]; gc[c] = gcoef[d]; }
    }
    for (int j = beg; j < end; j++) {
        float de = dist[eidx[j]];
#pragma unroll
        for (int c = 0; c < 10; c++) {
            int d = c * 32 + lane;
            if (d < DD) {
                float z = (de - gm[c]) * gi[c];
                acc[c] += __expf(-0.5f * z * z) * gc[c];
            }
        }
    }
    const float* sp = scale_param + degc * DD;
#pragma unroll
    for (int c = 0; c < 10; c++) {
        int d = c * 32 + lane;
        if (d < DD) h[(size_t)n * DD + d] += acc[c] * expf(sp[d]);
    }
}

// ---------------- attention fusion -> split "fused" ----------------
__global__ void attn_k(const int* __restrict__ x, const float* __restrict__ atom_emb,
                       const float* __restrict__ att_vec,
                       uint32_t* __restrict__ fh, uint32_t* __restrict__ fl) {
    int warp = (blockIdx.x * blockDim.x + threadIdx.x) >> 5;
    int lane = threadIdx.x & 31;
    if (warp >= NN) return;
    const int* xn = x + warp * 9;
    const float2* emb2 = (const float2*)atom_emb;
    const float2* av2 = (const float2*)att_vec;
    int ids[9];
#pragma unroll
    for (int f = 0; f < 9; f++) ids[f] = (f * 119 + xn[f]) * 150;
    float sc[9];
#pragma unroll
    for (int f = 0; f < 9; f++) {
        float p = 0.f;
        for (int pc = lane; pc < 150; pc += 32) {
            float2 e = emb2[ids[f] + pc];
            float2 a = av2[pc];
            p += e.x * a.x + e.y * a.y;
        }
#pragma unroll
        for (int o = 16; o > 0; o >>= 1) p += __shfl_xor_sync(0xffffffffu, p, o);
        sc[f] = p;
    }
    float m = sc[0];
#pragma unroll
    for (int f = 1; f < 9; f++) m = fmaxf(m, sc[f]);
    float s = 0.f;
#pragma unroll
    for (int f = 0; f < 9; f++) { sc[f] = __expf(sc[f] - m); s += sc[f]; }
    float inv = 1.f / s;
    for (int pc = lane; pc < 150; pc += 32) {
        float2 a = make_float2(0.f, 0.f);
#pragma unroll
        for (int f = 0; f < 9; f++) {
            float2 e = emb2[ids[f] + pc];
            a.x += sc[f] * e.x;
            a.y += sc[f] * e.y;
        }
        uint32_t hi, lo;
        split2(a.x * inv, a.y * inv, hi, lo);
        fh[(size_t)warp * SP300 + pc] = hi;
        fl[(size_t)warp * SP300 + pc] = lo;
    }
}

// ---------------- CSR aggregation with inline BN(+relu) ----------------
__global__ void gather_k(const float* __restrict__ h,
                         const int* __restrict__ rowptr, const int* __restrict__ eidx,
                         const int* __restrict__ src, const int* __restrict__ attr,
                         const float* __restrict__ E0, const float* __restrict__ E1,
                         const float* __restrict__ E2,
                         const float* __restrict__ mu, const float* __restrict__ istd,
                         const float* __restrict__ gamma, const float* __restrict__ beta,
                         int apply_bn,
                         uint32_t* __restrict__ aggh, uint32_t* __restrict__ aggl) {
    int n = (blockIdx.x * blockDim.x + threadIdx.x) >> 5;
    int lane = threadIdx.x & 31;
    if (n >= NN) return;
    int beg = rowptr[n], end = rowptr[n + 1];
    const float2* h2 = (const float2*)h;
    const float2* e02 = (const float2*)(E0 + 4 * DD);
    const float2* e12 = (const float2*)E1;
    const float2* e22 = (const float2*)E2;

    float2 scv[5], shv[5];
#pragma unroll
    for (int c = 0; c < 5; c++) {
        int pc = c * 32 + lane;
        if (pc < 150 && apply_bn) {
            float2 g = ((const float2*)gamma)[pc];
            float2 b = ((const float2*)beta)[pc];
            float2 m = ((const float2*)mu)[pc];
            float2 is = ((const float2*)istd)[pc];
            scv[c].x = g.x * is.x; scv[c].y = g.y * is.y;
            shv[c].x = b.x - m.x * scv[c].x; shv[c].y = b.y - m.y * scv[c].y;
        }
    }

    float2 acc[5];
#pragma unroll
    for (int c = 0; c < 5; c++) {
        int pc = c * 32 + lane;
        if (pc < 150) {
            float2 v = h2[(size_t)n * 150 + pc];
            if (apply_bn) {
                v.x = fmaxf(v.x * scv[c].x + shv[c].x, 0.f);
                v.y = fmaxf(v.y * scv[c].y + shv[c].y, 0.f);
            }
            float2 s0 = e02[pc], s1 = e12[pc], s2 = e22[pc];
            acc[c].x = v.x + s0.x + s1.x + s2.x;
            acc[c].y = v.y + s0.y + s1.y + s2.y;
        }
    }
    for (int j = beg; j < end; j++) {
        int e = eidx[j];
        int s = src[e];
        int a0 = attr[e * 3 + 0], a1 = attr[e * 3 + 1], a2 = attr[e * 3 + 2];
        const float2* hs = h2 + (size_t)s * 150;
        const float2* p0 = (const float2*)(E0 + a0 * DD);
        const float2* p1 = (const float2*)(E1 + a1 * DD);
        const float2* p2 = (const float2*)(E2 + a2 * DD);
#pragma unroll
        for (int c = 0; c < 5; c++) {
            int pc = c * 32 + lane;
            if (pc < 150) {
                float2 v = hs[pc];
                if (apply_bn) {
                    v.x = fmaxf(v.x * scv[c].x + shv[c].x, 0.f);
                    v.y = fmaxf(v.y * scv[c].y + shv[c].y, 0.f);
                }
                float2 q0 = p0[pc], q1 = p1[pc], q2 = p2[pc];
                acc[c].x += v.x + q0.x + q1.x + q2.x;
                acc[c].y += v.y + q0.y + q1.y + q2.y;
            }
        }
    }
#pragma unroll
    for (int c = 0; c < 5; c++) {
        int pc = c * 32 + lane;
        if (pc < 150) {
            uint32_t hi, lo;
            split2(acc[c].x, acc[c].y, hi, lo);
            aggh[(size_t)n * SP300 + pc] = hi;
            aggl[(size_t)n * SP300 + pc] = lo;
        }
    }
}

// ---------------- batchnorm ----------------
#define BN_RPB 128
__global__ void bn_stats_k(const float* __restrict__ h, float* stats) {
    int row0 = blockIdx.x * BN_RPB;
    int rend = min(row0 + BN_RPB, NN);
    int c0 = threadIdx.x;
    int c1 = threadIdx.x + 256;
    float s0 = 0.f, q0 = 0.f, s1 = 0.f, q1 = 0.f;
    for (int r = row0; r < rend; r++) {
        float v0 = h[(size_t)r * DD + c0];
        s0 += v0; q0 += v0 * v0;
        if (c1 < DD) {
            float v1 = h[(size_t)r * DD + c1];
            s1 += v1; q1 += v1 * v1;
        }
    }
    atomicAdd(&stats[c0], s0);
    atomicAdd(&stats[DD + c0], q0);
    if (c1 < DD) {
        atomicAdd(&stats[c1], s1);
        atomicAdd(&stats[DD + c1], q1);
    }
}
__global__ void bn_fin_k(const float* __restrict__ stats, float* mu, float* istd, float* stats_z) {
    int d = blockIdx.x * blockDim.x + threadIdx.x;
    if (d < DD) {
        float m = stats[d] / (float)NN;
        float v = stats[DD + d] / (float)NN - m * m;
        v = fmaxf(v, 0.f);
        mu[d] = m;
        istd[d] = rsqrtf(v + BN_EPS);
        stats_z[d] = 0.f;
        stats_z[DD + d] = 0.f;
    }
}

// ---------------- pooling with inline BN (last layer) ----------------
__global__ void gstart_k(const int* __restrict__ batch, int* gstart) {
    int g = blockIdx.x * blockDim.x + threadIdx.x;
    if (g > GG) return;
    int lo = 0, hi = NN;
    while (lo < hi) {
        int mid = (lo + hi) >> 1;
        if (batch[mid] < g) lo = mid + 1; else hi = mid;
    }
    gstart[g] = lo;
}
__global__ void pool_k(const float* __restrict__ h, const int* __restrict__ gstart,
                       const float* __restrict__ mu, const float* __restrict__ istd,
                       const float* __restrict__ gamma, const float* __restrict__ beta,
                       uint32_t* __restrict__ hgh, uint32_t* __restrict__ hgl) {
    int g = blockIdx.x;
    int pc = threadIdx.x;
    if (pc >= 150) return;
    const float2* h2 = (const float2*)h;
    float2 gm = ((const float2*)gamma)[pc];
    float2 bt = ((const float2*)beta)[pc];
    float2 m = ((const float2*)mu)[pc];
    float2 is = ((const float2*)istd)[pc];
    float2 sc, sh;
    sc.x = gm.x * is.x; sc.y = gm.y * is.y;
    sh.x = bt.x - m.x * sc.x; sh.y = bt.y - m.y * sc.y;
    int s = gstart[g], e = gstart[g + 1];
    float2 a = make_float2(0.f, 0.f);
    for (int r = s; r < e; r++) {
        float2 v = h2[(size_t)r * 150 + pc];
        a.x += v.x * sc.x + sh.x;
        a.y += v.y * sc.y + sh.y;
    }
    float inv = 1.f / fmaxf((float)(e - s), 1.f);
    uint32_t hi, lo;
    split2(a.x * inv, a.y * inv, hi, lo);
    hgh[(size_t)g * SP300 + pc] = hi;
    hgl[(size_t)g * SP300 + pc] = lo;
}

// ---------------- host ----------------
static float* symf(const void* sym) { void* p = nullptr; cudaGetSymbolAddress(&p, sym); return (float*)p; }
static int* symi(const void* sym) { void* p = nullptr; cudaGetSymbolAddress(&p, sym); return (int*)p; }
static uint32_t* symu(const void* sym) { void* p = nullptr; cudaGetSymbolAddress(&p, sym); return (uint32_t*)p; }
static inline int cdiv(int a, int b) { return (a + b - 1) / b; }

extern "C" void kernel_launch(void* const* d_in, const int* in_sizes, int n_in,
                              void* d_out, int out_size) {
    const int* x            = (const int*)d_in[0];
    const int* edge_index   = (const int*)d_in[1];
    const int* edge_attr    = (const int*)d_in[2];
    const float* edge_dist  = (const float*)d_in[3];
    const int* batch        = (const int*)d_in[4];
    const float* atom_emb   = (const float*)d_in[5];
    const float* att_vec    = (const float*)d_in[6];
    const float* out_lin_w  = (const float*)d_in[7];
    const float* out_lin_b  = (const float*)d_in[8];
    const float* g_means    = (const float*)d_in[9];
    const float* g_stds     = (const float*)d_in[10];
    const float* scale_par  = (const float*)d_in[11];
    const float* edge_emb   = (const float*)d_in[12];
    const float* mlp_w1     = (const float*)d_in[13];
    const float* mlp_b1     = (const float*)d_in[14];
    const float* mlp_w2     = (const float*)d_in[15];
    const float* mlp_b2     = (const float*)d_in[16];
    const float* bn_gamma   = (const float*)d_in[17];
    const float* bn_beta    = (const float*)d_in[18];
    const float* feat_w     = (const float*)d_in[19];
    const float* feat_b     = (const float*)d_in[20];
    const float* ol_w1      = (const float*)d_in[21];
    const float* ol_b1      = (const float*)d_in[22];
    const float* ol_w2      = (const float*)d_in[23];
    const float* ol_b2      = (const float*)d_in[24];

    const int* e_src = edge_index;
    const int* e_dst = edge_index + EE;

    float* h      = symf(d_h);
    int*   counts = symi(d_counts);
    int*   cursor = symi(d_cursor);
    int*   rowptr = symi(d_rowptr);
    int*   part   = symi(d_part);
    int*   bsum   = symi(d_bsum);
    int*   eidx   = symi(d_eidx);
    int*   gstart = symi(d_gstart);
    float* stats  = symf(d_stats);
    float* mu     = symf(d_mu);
    float* istd   = symf(d_istd);
    float* ginv   = symf(d_ginv);
    float* gcoef  = symf(d_gcoef);
    uint32_t* aggh = symu(d_aggh), *aggl = symu(d_aggl);
    uint32_t* hidh = symu(d_hidh), *hidl = symu(d_hidl);
    uint32_t* hgh = symu(d_hgh), *hgl = symu(d_hgl);
    uint32_t* hfh = symu(d_hfh), *hfl = symu(d_hfl);
    uint32_t* tbh = symu(d_tbh), *tbl = symu(d_tbl);
    uint32_t* bt0h = symu(d_bt0h), *bt0l = symu(d_bt0l);
    uint32_t* bt1h = symu(d_bt1h), *bt1l = symu(d_bt1l);
    uint32_t* bt2h = symu(d_bt2h), *bt2l = symu(d_bt2l);
    uint32_t* bt3h = symu(d_bt3h), *bt3l = symu(d_bt3l);
    uint32_t* bt4h = symu(d_bt4h), *bt4l = symu(d_bt4l);
    uint32_t* bt5h = symu(d_bt5h), *bt5l = symu(d_bt5l);

    float* out_hfeat = (float*)d_out;
    float* out_final = (float*)d_out + GG * FT;

    const int T = 256;
    cudaFuncSetAttribute(gemm128_k, cudaFuncAttributeMaxDynamicSharedMemorySize, GEMM128_SMEM);
    cudaFuncSetAttribute(gemm64_k, cudaFuncAttributeMaxDynamicSharedMemorySize, GEMM64_SMEM);

    // launch 1: fused weight prep
    {
        PrepArgs pa;
        pa.s[0] = { out_lin_w, bt0h, bt0l, DD, DD, SP300 };
        for (int l = 0; l < LL; l++) {
            pa.s[1 + l] = { mlp_w1 + (size_t)l * DD * D2,
                            bt1h + (size_t)l * D2 * SP300, bt1l + (size_t)l * D2 * SP300,
                            DD, D2, SP300 };
            pa.s[6 + l] = { mlp_w2 + (size_t)l * D2 * DD,
                            bt2h + (size_t)l * DD * SP600, bt2l + (size_t)l * DD * SP600,
                            D2, DD, SP600 };
        }
        pa.s[11] = { feat_w, bt3h, bt3l, DD, FT, SP300 };
        pa.s[12] = { ol_w1, bt4h, bt4l, FT, FT, SP512 };
        pa.s[13] = { ol_w2, bt5h, bt5l, FT, FT / 2, SP512 };
        dim3 g(cdiv(FT * SP512, T), 14);
        prep_all_k<<<g, T>>>(pa);
    }
    // launch 2: attention fusion
    attn_k<<<cdiv(NN * 32, T), T>>>(x, atom_emb, att_vec, aggh, aggl);
    // launch 3
    zero_i<<<cdiv(NN, T), T>>>(counts, NN);
    // launch 4 (ncu sample target): layer-0 GEMM, Nc=300 -> BN=64 ldmatrix variant
    {
        dim3 g(cdiv(DD, 64), cdiv(NN, 128));
        gemm64_k<<<g, 128, GEMM64_SMEM>>>(aggh, aggl, bt0h, bt0l, out_lin_b, nullptr,
                                          h, nullptr, nullptr, NN, DD, SP300, 0, 0, 0);
    }
    // CSR build
    count_k<<<cdiv(EE, T), T>>>(e_dst, counts);
    scan1_k<<<cdiv(NN, 1024), 1024>>>(counts, part, bsum);
    scan2_k<<<1, 32>>>(bsum, cdiv(NN, 1024));
    scan3_k<<<cdiv(NN, T), T>>>(part, bsum, rowptr);
    zero_i<<<cdiv(NN, T), T>>>(cursor, NN);
    fill_k<<<cdiv(EE, T), T>>>(e_dst, rowptr, cursor, eidx);
    // gaussian basis adds into h
    gauss_pre_k<<<cdiv(DD, T), T>>>(g_stds, ginv, gcoef);
    gauss_csr_k<<<cdiv(NN * 32, T), T>>>(edge_dist, rowptr, eidx, g_means, ginv, gcoef,
                                         scale_par, h);

    // --- L layers ---
    for (int l = 0; l < LL; l++) {
        const float* E0 = edge_emb + (size_t)(l * 3 + 0) * 5 * DD;
        const float* E1 = edge_emb + (size_t)(l * 3 + 1) * 5 * DD;
        const float* E2 = edge_emb + (size_t)(l * 3 + 2) * 5 * DD;
        gather_k<<<cdiv(NN * 32, T), T>>>(h, rowptr, eidx, e_src, edge_attr, E0, E1, E2,
                                          mu, istd, bn_gamma + (l - 1) * DD, bn_beta + (l - 1) * DD,
                                          (l > 0) ? 1 : 0, aggh, aggl);
        {
            // w1: Nc=600 -> BN=128 variant
            dim3 g1(cdiv(D2, 128), cdiv(NN, 128));
            gemm128_k<<<g1, 256, GEMM128_SMEM>>>(aggh, aggl,
                                                 bt1h + (size_t)l * D2 * SP300,
                                                 bt1l + (size_t)l * D2 * SP300,
                                                 mlp_b1 + l * D2, nullptr,
                                                 nullptr, hidh, hidl, NN, D2, SP300, SP600, 1, 0);
            // w2: Nc=300 -> BN=64 ldmatrix variant
            dim3 g2(cdiv(DD, 64), cdiv(NN, 128));
            gemm64_k<<<g2, 128, GEMM64_SMEM>>>(hidh, hidl,
                                               bt2h + (size_t)l * DD * SP600,
                                               bt2l + (size_t)l * DD * SP600,
                                               mlp_b2 + l * DD, nullptr,
                                               h, nullptr, nullptr, NN, DD, SP600, 0, 0, 0);
        }
        bn_stats_k<<<cdiv(NN, BN_RPB), 256>>>(h, stats);
        bn_fin_k<<<cdiv(DD, T), T>>>(stats, mu, istd, stats);
    }

    // --- pooling with inline BN of last layer ---
    gstart_k<<<cdiv(GG + 1, T), T>>>(batch, gstart);
    pool_k<<<GG, 160>>>(h, gstart, mu, istd, bn_gamma + (LL - 1) * DD, bn_beta + (LL - 1) * DD,
                        hgh, hgl);

    // --- head (BN=128 variant) ---
    {
        dim3 g(cdiv(FT, 128), cdiv(GG, 128));
        gemm128_k<<<g, 256, GEMM128_SMEM>>>(hgh, hgl, bt3h, bt3l, feat_b, nullptr,
                                            out_hfeat, hfh, hfl, GG, FT, SP300, SP512, 0, 0);
    }
    {
        dim3 g(cdiv(FT, 128), cdiv(GG, 128));
        gemm128_k<<<g, 256, GEMM128_SMEM>>>(hfh, hfl, bt4h, bt4l, ol_b1, nullptr,
                                            nullptr, tbh, tbl, GG, FT, SP512, SP512, 1, 0);
    }
    {
        dim3 g(cdiv(FT / 2, 128), cdiv(GG, 128));
        gemm128_k<<<g, 256, GEMM128_SMEM>>>(tbh, tbl, bt5h, bt5l, ol_b2, nullptr,
                                            out_final, nullptr, nullptr, GG, FT / 2, SP512, 0, 0, 0);
    }
}

// round 17
// speedup vs baseline: 1.1323x; 1.0377x over previous
#include <cuda_runtime.h>
#include <cuda_bf16.h>
#include <math.h>
#include <stdint.h>

#define NN 100000
#define EE 200000
#define GG 2000
#define DD 300
#define D2 600
#define LL 5
#define FT 512
#define MAXDEG 4
#define BN_EPS 1e-5f

#define SP300 152
#define SP600 304
#define SP512 256

// ---------------- scratch (device globals; no allocation) ----------------
__device__ float d_h[NN * DD];
__device__ int   d_counts[NN];
__device__ int   d_cursor[NN];
__device__ int   d_rowptr[NN + 1];
__device__ int   d_part[NN];
__device__ int   d_bsum[128];
__device__ int   d_eidx[EE];
__device__ int   d_gstart[GG + 1];
__device__ float d_stats[2 * DD];
__device__ float d_mu[DD];
__device__ float d_istd[DD];
__device__ float d_ginv[DD];
__device__ float d_gcoef[DD];
__device__ uint32_t d_aggh[NN * SP300], d_aggl[NN * SP300];
__device__ uint32_t d_hidh[NN * SP600], d_hidl[NN * SP600];
__device__ uint32_t d_hgh[GG * SP300],  d_hgl[GG * SP300];
__device__ uint32_t d_hfh[GG * SP512],  d_hfl[GG * SP512];
__device__ uint32_t d_tbh[GG * SP512],  d_tbl[GG * SP512];
__device__ uint32_t d_bt0h[DD * SP300],          d_bt0l[DD * SP300];
__device__ uint32_t d_bt1h[LL * D2 * SP300],     d_bt1l[LL * D2 * SP300];
__device__ uint32_t d_bt2h[LL * DD * SP600],     d_bt2l[LL * DD * SP600];
__device__ uint32_t d_bt3h[FT * SP300],          d_bt3l[FT * SP300];
__device__ uint32_t d_bt4h[FT * SP512],          d_bt4l[FT * SP512];
__device__ uint32_t d_bt5h[(FT / 2) * SP512],    d_bt5l[(FT / 2) * SP512];

// ---------------- helpers ----------------
__device__ __forceinline__ uint32_t smem_u32(const void* p) {
    uint32_t a;
    asm("{ .reg .u64 t; cvta.to.shared.u64 t, %1; cvt.u32.u64 %0, t; }" : "=r"(a) : "l"(p));
    return a;
}
__device__ __forceinline__ void cp16(uint32_t dst, const void* src, int valid) {
    int sz = valid ? 16 : 0;
    asm volatile("cp.async.cg.shared.global [%0], [%1], 16, %2;" :: "r"(dst), "l"(src), "r"(sz) : "memory");
}
#define CP_COMMIT() asm volatile("cp.async.commit_group;" ::: "memory")
#define CP_WAIT(n)  asm volatile("cp.async.wait_group %0;" :: "n"(n) : "memory")

__device__ __forceinline__ void split2(float x0, float x1, uint32_t& hi, uint32_t& lo) {
    asm("cvt.rn.bf16x2.f32 %0, %1, %2;" : "=r"(hi) : "f"(x1), "f"(x0));
    float h0 = __uint_as_float(hi << 16);
    float h1 = __uint_as_float(hi & 0xFFFF0000u);
    float l0 = x0 - h0, l1 = x1 - h1;
    asm("cvt.rn.bf16x2.f32 %0, %1, %2;" : "=r"(lo) : "f"(l1), "f"(l0));
}
__device__ __forceinline__ void mma_bf16(float* c, const uint32_t* a, const uint32_t* b) {
    asm("mma.sync.aligned.m16n8k16.row.col.f32.bf16.bf16.f32 "
        "{%0,%1,%2,%3}, {%4,%5,%6,%7}, {%8,%9}, {%0,%1,%2,%3};"
        : "+f"(c[0]), "+f"(c[1]), "+f"(c[2]), "+f"(c[3])
        : "r"(a[0]), "r"(a[1]), "r"(a[2]), "r"(a[3]), "r"(b[0]), "r"(b[1]));
}
__device__ __forceinline__ void ldsm4(uint32_t& r0, uint32_t& r1, uint32_t& r2, uint32_t& r3,
                                      uint32_t addr) {
    asm volatile("ldmatrix.sync.aligned.m8n8.x4.shared.b16 {%0,%1,%2,%3}, [%4];"
                 : "=r"(r0), "=r"(r1), "=r"(r2), "=r"(r3) : "r"(addr));
}

#define SS 12

// ================ GEMM variant A: 256 threads, BM=128 x BN=128, ldmatrix frags ================
#define SM_CH 1536
#define G_STAGES 3
#define GEMM128_SMEM (G_STAGES * 4 * SM_CH * 4)   // 73728 B

__global__ __launch_bounds__(256, 2) void gemm128_k(
    const uint32_t* __restrict__ Ah, const uint32_t* __restrict__ Al,
    const uint32_t* __restrict__ Bh, const uint32_t* __restrict__ Bl,
    const float* __restrict__ bias, const float* __restrict__ add,
    float* __restrict__ C, uint32_t* __restrict__ Oh, uint32_t* __restrict__ Ol,
    int M, int Nc, int SP, int SPo, int relu, int has_add) {
    extern __shared__ uint32_t sm[];
    int tid = threadIdx.x, lane = tid & 31, wid = tid >> 5;
    int wm = wid & 1, wn = wid >> 1;
    int bnc = blockIdx.x * 128;
    int bm = blockIdx.y * 128;
    int nch = SP >> 3;

    float acc[4][4][4];
#pragma unroll
    for (int i = 0; i < 4; i++)
#pragma unroll
        for (int j = 0; j < 4; j++)
#pragma unroll
            for (int r = 0; r < 4; r++) acc[i][j][r] = 0.f;

    int lr = tid >> 1, lg = tid & 1;
    auto load_chunk = [&](int c, int s) {
        uint32_t* base = sm + s * 4 * SM_CH;
        int gu = c * 8 + lg * 4;
        int gr = bm + lr, br = bnc + lr;
        uint32_t off = smem_u32(base + lr * SS + lg * 4);
        int va = gr < M, vb = br < Nc;
        cp16(off,                 Ah + (size_t)gr * SP + gu, va);
        cp16(off + SM_CH * 4,     Al + (size_t)gr * SP + gu, va);
        cp16(off + 2 * SM_CH * 4, Bh + (size_t)br * SP + gu, vb);
        cp16(off + 3 * SM_CH * 4, Bl + (size_t)br * SP + gu, vb);
    };

    load_chunk(0, 0);
    CP_COMMIT();
    if (1 < nch) load_chunk(1, 1);
    CP_COMMIT();

    // ldmatrix lane addressing (R16-proven quadrant mapping)
    int g8 = lane >> 3, l8 = lane & 7;
    uint32_t aOff = (uint32_t)(wm * 64 + ((g8 & 1) << 3) + l8) * (SS * 4) + ((g8 >> 1) << 4);
    uint32_t bOff = (uint32_t)(wn * 32 + ((g8 >> 1) << 3) + l8) * (SS * 4) + ((g8 & 1) << 4);
    uint32_t smBase = smem_u32(sm);

    int row = lane >> 2, qc = lane & 3;
    for (int c = 0; c < nch; c++) {
        CP_WAIT(1);
        __syncthreads();
        {
            int n2 = c + 2;
            if (n2 < nch) load_chunk(n2, n2 % G_STAGES);
            CP_COMMIT();
        }
        uint32_t chunkBase = smBase + (uint32_t)(c % G_STAGES) * 4 * SM_CH * 4;
        uint32_t bfh[4][2], bfl[4][2];
        {
            uint32_t ba = chunkBase + 2 * SM_CH * 4 + bOff;
            ldsm4(bfh[0][0], bfh[0][1], bfh[1][0], bfh[1][1], ba);
            ldsm4(bfh[2][0], bfh[2][1], bfh[3][0], bfh[3][1], ba + 16 * SS * 4);
            uint32_t bb = chunkBase + 3 * SM_CH * 4 + bOff;
            ldsm4(bfl[0][0], bfl[0][1], bfl[1][0], bfl[1][1], bb);
            ldsm4(bfl[2][0], bfl[2][1], bfl[3][0], bfl[3][1], bb + 16 * SS * 4);
        }
#pragma unroll
        for (int mt = 0; mt < 4; mt++) {
            uint32_t ah[4], al[4];
            uint32_t aa = chunkBase + aOff + (uint32_t)mt * 16 * SS * 4;
            ldsm4(ah[0], ah[1], ah[2], ah[3], aa);
            ldsm4(al[0], al[1], al[2], al[3], aa + SM_CH * 4);
#pragma unroll
            for (int nt = 0; nt < 4; nt++) mma_bf16(acc[mt][nt], ah, bfl[nt]);
#pragma unroll
            for (int nt = 0; nt < 4; nt++) mma_bf16(acc[mt][nt], al, bfh[nt]);
#pragma unroll
            for (int nt = 0; nt < 4; nt++) mma_bf16(acc[mt][nt], ah, bfh[nt]);
        }
    }

#pragma unroll
    for (int mt = 0; mt < 4; mt++) {
#pragma unroll
        for (int nt = 0; nt < 4; nt++) {
#pragma unroll
            for (int half = 0; half < 2; half++) {
                int gr = bm + wm * 64 + mt * 16 + row + half * 8;
                if (gr >= M) continue;
                int gc0 = bnc + wn * 32 + nt * 8 + qc * 2;
                if (gc0 >= Nc) continue;
                float v0 = acc[mt][nt][half * 2 + 0] + bias[gc0];
                float v1 = acc[mt][nt][half * 2 + 1] + bias[gc0 + 1];
                if (has_add) {
                    v0 += add[(size_t)gr * Nc + gc0];
                    v1 += add[(size_t)gr * Nc + gc0 + 1];
                }
                if (relu) { v0 = fmaxf(v0, 0.f); v1 = fmaxf(v1, 0.f); }
                if (C) {
                    C[(size_t)gr * Nc + gc0] = v0;
                    C[(size_t)gr * Nc + gc0 + 1] = v1;
                }
                if (Oh) {
                    uint32_t hi, lo;
                    split2(v0, v1, hi, lo);
                    int p = gc0 >> 1;
                    Oh[(size_t)gr * SPo + p] = hi;
                    Ol[(size_t)gr * SPo + p] = lo;
                }
            }
        }
    }
}

// ================ GEMM variant B: 128 threads, BM=128 x BN=64, ldmatrix frags (Nc=300) ================
#define A_CH 1536
#define B_CH 768
#define ST_CH (2 * A_CH + 2 * B_CH)
#define GEMM64_SMEM (G_STAGES * ST_CH * 4)   // 55296 B

__global__ __launch_bounds__(128, 4) void gemm64_k(
    const uint32_t* __restrict__ Ah, const uint32_t* __restrict__ Al,
    const uint32_t* __restrict__ Bh, const uint32_t* __restrict__ Bl,
    const float* __restrict__ bias, const float* __restrict__ add,
    float* __restrict__ C, uint32_t* __restrict__ Oh, uint32_t* __restrict__ Ol,
    int M, int Nc, int SP, int SPo, int relu, int has_add) {
    extern __shared__ uint32_t sm[];
    int tid = threadIdx.x, lane = tid & 31, wid = tid >> 5;
    int wm = wid & 1, wn = wid >> 1;
    int bnc = blockIdx.x * 64;
    int bm = blockIdx.y * 128;
    int nch = SP >> 3;

    float acc[4][4][4];
#pragma unroll
    for (int i = 0; i < 4; i++)
#pragma unroll
        for (int j = 0; j < 4; j++)
#pragma unroll
            for (int r = 0; r < 4; r++) acc[i][j][r] = 0.f;

    auto load_chunk = [&](int c, int s) {
        uint32_t* base = sm + s * ST_CH;
        int gu = c * 8;
#pragma unroll
        for (int it = 0; it < 2; it++) {
            int i = tid + it * 128;
            int r = i >> 1, g = i & 1;
            int gr = bm + r;
            uint32_t off = smem_u32(base + r * SS + g * 4);
            int va = gr < M;
            cp16(off,            Ah + (size_t)gr * SP + gu + g * 4, va);
            cp16(off + A_CH * 4, Al + (size_t)gr * SP + gu + g * 4, va);
        }
        {
            int r = tid >> 1, g = tid & 1;
            int br = bnc + r;
            uint32_t off = smem_u32(base + 2 * A_CH + r * SS + g * 4);
            int vb = br < Nc;
            cp16(off,            Bh + (size_t)br * SP + gu + g * 4, vb);
            cp16(off + B_CH * 4, Bl + (size_t)br * SP + gu + g * 4, vb);
        }
    };

    load_chunk(0, 0);
    CP_COMMIT();
    if (1 < nch) load_chunk(1, 1);
    CP_COMMIT();

    int g8 = lane >> 3, l8 = lane & 7;
    uint32_t aOff = (uint32_t)(wm * 64 + ((g8 & 1) << 3) + l8) * (SS * 4) + ((g8 >> 1) << 4);
    uint32_t bOff = (uint32_t)(wn * 32 + ((g8 >> 1) << 3) + l8) * (SS * 4) + ((g8 & 1) << 4);
    uint32_t smBase = smem_u32(sm);

    int row = lane >> 2, qc = lane & 3;
    for (int c = 0; c < nch; c++) {
        CP_WAIT(1);
        __syncthreads();
        {
            int n2 = c + 2;
            if (n2 < nch) load_chunk(n2, n2 % G_STAGES);
            CP_COMMIT();
        }
        uint32_t chunkBase = smBase + (uint32_t)(c % G_STAGES) * ST_CH * 4;
        uint32_t bfh[4][2], bfl[4][2];
        {
            uint32_t ba = chunkBase + 2 * A_CH * 4 + bOff;
            ldsm4(bfh[0][0], bfh[0][1], bfh[1][0], bfh[1][1], ba);
            ldsm4(bfh[2][0], bfh[2][1], bfh[3][0], bfh[3][1], ba + 16 * SS * 4);
            uint32_t bb = chunkBase + (2 * A_CH + B_CH) * 4 + bOff;
            ldsm4(bfl[0][0], bfl[0][1], bfl[1][0], bfl[1][1], bb);
            ldsm4(bfl[2][0], bfl[2][1], bfl[3][0], bfl[3][1], bb + 16 * SS * 4);
        }
#pragma unroll
        for (int mt = 0; mt < 4; mt++) {
            uint32_t ah[4], al[4];
            uint32_t aa = chunkBase + aOff + (uint32_t)mt * 16 * SS * 4;
            ldsm4(ah[0], ah[1], ah[2], ah[3], aa);
            ldsm4(al[0], al[1], al[2], al[3], aa + A_CH * 4);
#pragma unroll
            for (int nt = 0; nt < 4; nt++) mma_bf16(acc[mt][nt], ah, bfl[nt]);
#pragma unroll
            for (int nt = 0; nt < 4; nt++) mma_bf16(acc[mt][nt], al, bfh[nt]);
#pragma unroll
            for (int nt = 0; nt < 4; nt++) mma_bf16(acc[mt][nt], ah, bfh[nt]);
        }
    }

#pragma unroll
    for (int mt = 0; mt < 4; mt++) {
#pragma unroll
        for (int nt = 0; nt < 4; nt++) {
#pragma unroll
            for (int half = 0; half < 2; half++) {
                int gr = bm + wm * 64 + mt * 16 + row + half * 8;
                if (gr >= M) continue;
                int gc0 = bnc + wn * 32 + nt * 8 + qc * 2;
                if (gc0 >= Nc) continue;
                float v0 = acc[mt][nt][half * 2 + 0] + bias[gc0];
                float v1 = acc[mt][nt][half * 2 + 1] + bias[gc0 + 1];
                if (has_add) {
                    v0 += add[(size_t)gr * Nc + gc0];
                    v1 += add[(size_t)gr * Nc + gc0 + 1];
                }
                if (relu) { v0 = fmaxf(v0, 0.f); v1 = fmaxf(v1, 0.f); }
                if (C) {
                    C[(size_t)gr * Nc + gc0] = v0;
                    C[(size_t)gr * Nc + gc0 + 1] = v1;
                }
                if (Oh) {
                    uint32_t hi, lo;
                    split2(v0, v1, hi, lo);
                    int p = gc0 >> 1;
                    Oh[(size_t)gr * SPo + p] = hi;
                    Ol[(size_t)gr * SPo + p] = lo;
                }
            }
        }
    }
}

// ---------------- fused weight prep ----------------
struct PrepSeg { const float* w; uint32_t* oh; uint32_t* ol; int K, N, SP; };
struct PrepArgs { PrepSeg s[14]; };

__global__ void prep_all_k(PrepArgs a) {
    PrepSeg p = a.s[blockIdx.y];
    int idx = blockIdx.x * blockDim.x + threadIdx.x;
    if (idx >= p.N * p.SP) return;
    int n = idx / p.SP, ku = idx % p.SP;
    int k0 = ku * 2, k1 = k0 + 1;
    float x0 = (k0 < p.K) ? p.w[(size_t)k0 * p.N + n] : 0.f;
    float x1 = (k1 < p.K) ? p.w[(size_t)k1 * p.N + n] : 0.f;
    uint32_t hi, lo;
    split2(x0, x1, hi, lo);
    p.oh[idx] = hi;
    p.ol[idx] = lo;
}

// ---------------- misc ----------------
__global__ void zero_i(int* p, int n) {
    int i = blockIdx.x * blockDim.x + threadIdx.x;
    if (i < n) p[i] = 0;
}
__global__ void count_k(const int* __restrict__ dst, int* counts) {
    int e = blockIdx.x * blockDim.x + threadIdx.x;
    if (e < EE) atomicAdd(&counts[dst[e]], 1);
}

// ---------------- CSR build ----------------
__global__ void scan1_k(const int* __restrict__ counts, int* part, int* bsum) {
    __shared__ int sh[1024];
    int tid = threadIdx.x;
    int i = blockIdx.x * 1024 + tid;
    int v = (i < NN) ? counts[i] : 0;
    sh[tid] = v;
    __syncthreads();
#pragma unroll
    for (int off = 1; off < 1024; off <<= 1) {
        int t = (tid >= off) ? sh[tid - off] : 0;
        __syncthreads();
        sh[tid] += t;
        __syncthreads();
    }
    if (i < NN) part[i] = sh[tid] - v;
    if (tid == 1023) bsum[blockIdx.x] = sh[1023];
}
__global__ void scan2_k(int* bsum, int nb) {
    if (threadIdx.x == 0 && blockIdx.x == 0) {
        int run = 0;
        for (int b = 0; b < nb; b++) { int t = bsum[b]; bsum[b] = run; run += t; }
    }
}
__global__ void scan3_k(const int* __restrict__ part, const int* __restrict__ bsum, int* rowptr) {
    int i = blockIdx.x * blockDim.x + threadIdx.x;
    if (i < NN) rowptr[i] = part[i] + bsum[i >> 10];
    if (i == 0) rowptr[NN] = EE;
}
__global__ void fill_k(const int* __restrict__ dst, const int* __restrict__ rowptr,
                       int* cursor, int* eidx) {
    int e = blockIdx.x * blockDim.x + threadIdx.x;
    if (e >= EE) return;
    int d = dst[e];
    int pos = atomicAdd(&cursor[d], 1);
    eidx[rowptr[d] + pos] = e;
}

// ---------------- gaussian basis: adds into h ----------------
__global__ void gauss_pre_k(const float* __restrict__ g_stds, float* ginv, float* gcoef) {
    int d = blockIdx.x * blockDim.x + threadIdx.x;
    if (d < DD) {
        float s = fabsf(g_stds[d]) + 0.01f;
        float a = sqrtf(2.0f * 3.14159f);
        ginv[d] = 1.f / s;
        gcoef[d] = 1.f / (a * s);
    }
}
__global__ void gauss_csr_k(const float* __restrict__ dist, const int* __restrict__ rowptr,
                            const int* __restrict__ eidx,
                            const float* __restrict__ g_means,
                            const float* __restrict__ ginv, const float* __restrict__ gcoef,
                            const float* __restrict__ scale_param, float* __restrict__ h) {
    int n = (blockIdx.x * blockDim.x + threadIdx.x) >> 5;
    int lane = threadIdx.x & 31;
    if (n >= NN) return;
    int beg = rowptr[n], end = rowptr[n + 1];
    int degc = min(max(end - beg - 1, 0), MAXDEG - 1);
    float gm[10], gi[10], gc[10], acc[10];
#pragma unroll
    for (int c = 0; c < 10; c++) {
        int d = c * 32 + lane;
        acc[c] = 0.f;
        if (d < DD) { gm[c] = g_means[d]; gi[c] = ginv[d]; gc[c] = gcoef[d]; }
    }
    for (int j = beg; j < end; j++) {
        float de = dist[eidx[j]];
#pragma unroll
        for (int c = 0; c < 10; c++) {
            int d = c * 32 + lane;
            if (d < DD) {
                float z = (de - gm[c]) * gi[c];
                acc[c] += __expf(-0.5f * z * z) * gc[c];
            }
        }
    }
    const float* sp = scale_param + degc * DD;
#pragma unroll
    for (int c = 0; c < 10; c++) {
        int d = c * 32 + lane;
        if (d < DD) h[(size_t)n * DD + d] += acc[c] * expf(sp[d]);
    }
}

// ---------------- attention fusion -> split "fused" ----------------
__global__ void attn_k(const int* __restrict__ x, const float* __restrict__ atom_emb,
                       const float* __restrict__ att_vec,
                       uint32_t* __restrict__ fh, uint32_t* __restrict__ fl) {
    int warp = (blockIdx.x * blockDim.x + threadIdx.x) >> 5;
    int lane = threadIdx.x & 31;
    if (warp >= NN) return;
    const int* xn = x + warp * 9;
    const float2* emb2 = (const float2*)atom_emb;
    const float2* av2 = (const float2*)att_vec;
    int ids[9];
#pragma unroll
    for (int f = 0; f < 9; f++) ids[f] = (f * 119 + xn[f]) * 150;
    float sc[9];
#pragma unroll
    for (int f = 0; f < 9; f++) {
        float p = 0.f;
        for (int pc = lane; pc < 150; pc += 32) {
            float2 e = emb2[ids[f] + pc];
            float2 a = av2[pc];
            p += e.x * a.x + e.y * a.y;
        }
#pragma unroll
        for (int o = 16; o > 0; o >>= 1) p += __shfl_xor_sync(0xffffffffu, p, o);
        sc[f] = p;
    }
    float m = sc[0];
#pragma unroll
    for (int f = 1; f < 9; f++) m = fmaxf(m, sc[f]);
    float s = 0.f;
#pragma unroll
    for (int f = 0; f < 9; f++) { sc[f] = __expf(sc[f] - m); s += sc[f]; }
    float inv = 1.f / s;
    for (int pc = lane; pc < 150; pc += 32) {
        float2 a = make_float2(0.f, 0.f);
#pragma unroll
        for (int f = 0; f < 9; f++) {
            float2 e = emb2[ids[f] + pc];
            a.x += sc[f] * e.x;
            a.y += sc[f] * e.y;
        }
        uint32_t hi, lo;
        split2(a.x * inv, a.y * inv, hi, lo);
        fh[(size_t)warp * SP300 + pc] = hi;
        fl[(size_t)warp * SP300 + pc] = lo;
    }
}

// ---------------- CSR aggregation with inline BN(+relu) ----------------
__global__ void gather_k(const float* __restrict__ h,
                         const int* __restrict__ rowptr, const int* __restrict__ eidx,
                         const int* __restrict__ src, const int* __restrict__ attr,
                         const float* __restrict__ E0, const float* __restrict__ E1,
                         const float* __restrict__ E2,
                         const float* __restrict__ mu, const float* __restrict__ istd,
                         const float* __restrict__ gamma, const float* __restrict__ beta,
                         int apply_bn,
                         uint32_t* __restrict__ aggh, uint32_t* __restrict__ aggl) {
    int n = (blockIdx.x * blockDim.x + threadIdx.x) >> 5;
    int lane = threadIdx.x & 31;
    if (n >= NN) return;
    int beg = rowptr[n], end = rowptr[n + 1];
    const float2* h2 = (const float2*)h;
    const float2* e02 = (const float2*)(E0 + 4 * DD);
    const float2* e12 = (const float2*)E1;
    const float2* e22 = (const float2*)E2;

    float2 scv[5], shv[5];
#pragma unroll
    for (int c = 0; c < 5; c++) {
        int pc = c * 32 + lane;
        if (pc < 150 && apply_bn) {
            float2 g = ((const float2*)gamma)[pc];
            float2 b = ((const float2*)beta)[pc];
            float2 m = ((const float2*)mu)[pc];
            float2 is = ((const float2*)istd)[pc];
            scv[c].x = g.x * is.x; scv[c].y = g.y * is.y;
            shv[c].x = b.x - m.x * scv[c].x; shv[c].y = b.y - m.y * scv[c].y;
        }
    }

    float2 acc[5];
#pragma unroll
    for (int c = 0; c < 5; c++) {
        int pc = c * 32 + lane;
        if (pc < 150) {
            float2 v = h2[(size_t)n * 150 + pc];
            if (apply_bn) {
                v.x = fmaxf(v.x * scv[c].x + shv[c].x, 0.f);
                v.y = fmaxf(v.y * scv[c].y + shv[c].y, 0.f);
            }
            float2 s0 = e02[pc], s1 = e12[pc], s2 = e22[pc];
            acc[c].x = v.x + s0.x + s1.x + s2.x;
            acc[c].y = v.y + s0.y + s1.y + s2.y;
        }
    }
    for (int j = beg; j < end; j++) {
        int e = eidx[j];
        int s = src[e];
        int a0 = attr[e * 3 + 0], a1 = attr[e * 3 + 1], a2 = attr[e * 3 + 2];
        const float2* hs = h2 + (size_t)s * 150;
        const float2* p0 = (const float2*)(E0 + a0 * DD);
        const float2* p1 = (const float2*)(E1 + a1 * DD);
        const float2* p2 = (const float2*)(E2 + a2 * DD);
#pragma unroll
        for (int c = 0; c < 5; c++) {
            int pc = c * 32 + lane;
            if (pc < 150) {
                float2 v = hs[pc];
                if (apply_bn) {
                    v.x = fmaxf(v.x * scv[c].x + shv[c].x, 0.f);
                    v.y = fmaxf(v.y * scv[c].y + shv[c].y, 0.f);
                }
                float2 q0 = p0[pc], q1 = p1[pc], q2 = p2[pc];
                acc[c].x += v.x + q0.x + q1.x + q2.x;
                acc[c].y += v.y + q0.y + q1.y + q2.y;
            }
        }
    }
#pragma unroll
    for (int c = 0; c < 5; c++) {
        int pc = c * 32 + lane;
        if (pc < 150) {
            uint32_t hi, lo;
            split2(acc[c].x, acc[c].y, hi, lo);
            aggh[(size_t)n * SP300 + pc] = hi;
            aggl[(size_t)n * SP300 + pc] = lo;
        }
    }
}

// ---------------- batchnorm ----------------
#define BN_RPB 128
__global__ void bn_stats_k(const float* __restrict__ h, float* stats) {
    int row0 = blockIdx.x * BN_RPB;
    int rend = min(row0 + BN_RPB, NN);
    int c0 = threadIdx.x;
    int c1 = threadIdx.x + 256;
    float s0 = 0.f, q0 = 0.f, s1 = 0.f, q1 = 0.f;
    for (int r = row0; r < rend; r++) {
        float v0 = h[(size_t)r * DD + c0];
        s0 += v0; q0 += v0 * v0;
        if (c1 < DD) {
            float v1 = h[(size_t)r * DD + c1];
            s1 += v1; q1 += v1 * v1;
        }
    }
    atomicAdd(&stats[c0], s0);
    atomicAdd(&stats[DD + c0], q0);
    if (c1 < DD) {
        atomicAdd(&stats[c1], s1);
        atomicAdd(&stats[DD + c1], q1);
    }
}
__global__ void bn_fin_k(const float* __restrict__ stats, float* mu, float* istd, float* stats_z) {
    int d = blockIdx.x * blockDim.x + threadIdx.x;
    if (d < DD) {
        float m = stats[d] / (float)NN;
        float v = stats[DD + d] / (float)NN - m * m;
        v = fmaxf(v, 0.f);
        mu[d] = m;
        istd[d] = rsqrtf(v + BN_EPS);
        stats_z[d] = 0.f;
        stats_z[DD + d] = 0.f;
    }
}

// ---------------- pooling with inline BN (last layer) ----------------
__global__ void gstart_k(const int* __restrict__ batch, int* gstart) {
    int g = blockIdx.x * blockDim.x + threadIdx.x;
    if (g > GG) return;
    int lo = 0, hi = NN;
    while (lo < hi) {
        int mid = (lo + hi) >> 1;
        if (batch[mid] < g) lo = mid + 1; else hi = mid;
    }
    gstart[g] = lo;
}
__global__ void pool_k(const float* __restrict__ h, const int* __restrict__ gstart,
                       const float* __restrict__ mu, const float* __restrict__ istd,
                       const float* __restrict__ gamma, const float* __restrict__ beta,
                       uint32_t* __restrict__ hgh, uint32_t* __restrict__ hgl) {
    int g = blockIdx.x;
    int pc = threadIdx.x;
    if (pc >= 150) return;
    const float2* h2 = (const float2*)h;
    float2 gm = ((const float2*)gamma)[pc];
    float2 bt = ((const float2*)beta)[pc];
    float2 m = ((const float2*)mu)[pc];
    float2 is = ((const float2*)istd)[pc];
    float2 sc, sh;
    sc.x = gm.x * is.x; sc.y = gm.y * is.y;
    sh.x = bt.x - m.x * sc.x; sh.y = bt.y - m.y * sc.y;
    int s = gstart[g], e = gstart[g + 1];
    float2 a = make_float2(0.f, 0.f);
    for (int r = s; r < e; r++) {
        float2 v = h2[(size_t)r * 150 + pc];
        a.x += v.x * sc.x + sh.x;
        a.y += v.y * sc.y + sh.y;
    }
    float inv = 1.f / fmaxf((float)(e - s), 1.f);
    uint32_t hi, lo;
    split2(a.x * inv, a.y * inv, hi, lo);
    hgh[(size_t)g * SP300 + pc] = hi;
    hgl[(size_t)g * SP300 + pc] = lo;
}

// ---------------- host ----------------
static float* symf(const void* sym) { void* p = nullptr; cudaGetSymbolAddress(&p, sym); return (float*)p; }
static int* symi(const void* sym) { void* p = nullptr; cudaGetSymbolAddress(&p, sym); return (int*)p; }
static uint32_t* symu(const void* sym) { void* p = nullptr; cudaGetSymbolAddress(&p, sym); return (uint32_t*)p; }
static inline int cdiv(int a, int b) { return (a + b - 1) / b; }

extern "C" void kernel_launch(void* const* d_in, const int* in_sizes, int n_in,
                              void* d_out, int out_size) {
    const int* x            = (const int*)d_in[0];
    const int* edge_index   = (const int*)d_in[1];
    const int* edge_attr    = (const int*)d_in[2];
    const float* edge_dist  = (const float*)d_in[3];
    const int* batch        = (const int*)d_in[4];
    const float* atom_emb   = (const float*)d_in[5];
    const float* att_vec    = (const float*)d_in[6];
    const float* out_lin_w  = (const float*)d_in[7];
    const float* out_lin_b  = (const float*)d_in[8];
    const float* g_means    = (const float*)d_in[9];
    const float* g_stds     = (const float*)d_in[10];
    const float* scale_par  = (const float*)d_in[11];
    const float* edge_emb   = (const float*)d_in[12];
    const float* mlp_w1     = (const float*)d_in[13];
    const float* mlp_b1     = (const float*)d_in[14];
    const float* mlp_w2     = (const float*)d_in[15];
    const float* mlp_b2     = (const float*)d_in[16];
    const float* bn_gamma   = (const float*)d_in[17];
    const float* bn_beta    = (const float*)d_in[18];
    const float* feat_w     = (const float*)d_in[19];
    const float* feat_b     = (const float*)d_in[20];
    const float* ol_w1      = (const float*)d_in[21];
    const float* ol_b1      = (const float*)d_in[22];
    const float* ol_w2      = (const float*)d_in[23];
    const float* ol_b2      = (const float*)d_in[24];

    const int* e_src = edge_index;
    const int* e_dst = edge_index + EE;

    float* h      = symf(d_h);
    int*   counts = symi(d_counts);
    int*   cursor = symi(d_cursor);
    int*   rowptr = symi(d_rowptr);
    int*   part   = symi(d_part);
    int*   bsum   = symi(d_bsum);
    int*   eidx   = symi(d_eidx);
    int*   gstart = symi(d_gstart);
    float* stats  = symf(d_stats);
    float* mu     = symf(d_mu);
    float* istd   = symf(d_istd);
    float* ginv   = symf(d_ginv);
    float* gcoef  = symf(d_gcoef);
    uint32_t* aggh = symu(d_aggh), *aggl = symu(d_aggl);
    uint32_t* hidh = symu(d_hidh), *hidl = symu(d_hidl);
    uint32_t* hgh = symu(d_hgh), *hgl = symu(d_hgl);
    uint32_t* hfh = symu(d_hfh), *hfl = symu(d_hfl);
    uint32_t* tbh = symu(d_tbh), *tbl = symu(d_tbl);
    uint32_t* bt0h = symu(d_bt0h), *bt0l = symu(d_bt0l);
    uint32_t* bt1h = symu(d_bt1h), *bt1l = symu(d_bt1l);
    uint32_t* bt2h = symu(d_bt2h), *bt2l = symu(d_bt2l);
    uint32_t* bt3h = symu(d_bt3h), *bt3l = symu(d_bt3l);
    uint32_t* bt4h = symu(d_bt4h), *bt4l = symu(d_bt4l);
    uint32_t* bt5h = symu(d_bt5h), *bt5l = symu(d_bt5l);

    float* out_hfeat = (float*)d_out;
    float* out_final = (float*)d_out + GG * FT;

    const int T = 256;
    cudaFuncSetAttribute(gemm128_k, cudaFuncAttributeMaxDynamicSharedMemorySize, GEMM128_SMEM);
    cudaFuncSetAttribute(gemm64_k, cudaFuncAttributeMaxDynamicSharedMemorySize, GEMM64_SMEM);

    // launch 1: fused weight prep
    {
        PrepArgs pa;
        pa.s[0] = { out_lin_w, bt0h, bt0l, DD, DD, SP300 };
        for (int l = 0; l < LL; l++) {
            pa.s[1 + l] = { mlp_w1 + (size_t)l * DD * D2,
                            bt1h + (size_t)l * D2 * SP300, bt1l + (size_t)l * D2 * SP300,
                            DD, D2, SP300 };
            pa.s[6 + l] = { mlp_w2 + (size_t)l * D2 * DD,
                            bt2h + (size_t)l * DD * SP600, bt2l + (size_t)l * DD * SP600,
                            D2, DD, SP600 };
        }
        pa.s[11] = { feat_w, bt3h, bt3l, DD, FT, SP300 };
        pa.s[12] = { ol_w1, bt4h, bt4l, FT, FT, SP512 };
        pa.s[13] = { ol_w2, bt5h, bt5l, FT, FT / 2, SP512 };
        dim3 g(cdiv(FT * SP512, T), 14);
        prep_all_k<<<g, T>>>(pa);
    }
    // launch 2: attention fusion
    attn_k<<<cdiv(NN * 32, T), T>>>(x, atom_emb, att_vec, aggh, aggl);
    // launch 3
    zero_i<<<cdiv(NN, T), T>>>(counts, NN);
    // launch 4: layer-0 GEMM (Nc=300 -> gemm64)
    {
        dim3 g(cdiv(DD, 64), cdiv(NN, 128));
        gemm64_k<<<g, 128, GEMM64_SMEM>>>(aggh, aggl, bt0h, bt0l, out_lin_b, nullptr,
                                          h, nullptr, nullptr, NN, DD, SP300, 0, 0, 0);
    }
    // CSR build
    count_k<<<cdiv(EE, T), T>>>(e_dst, counts);
    scan1_k<<<cdiv(NN, 1024), 1024>>>(counts, part, bsum);
    scan2_k<<<1, 32>>>(bsum, cdiv(NN, 1024));
    scan3_k<<<cdiv(NN, T), T>>>(part, bsum, rowptr);
    zero_i<<<cdiv(NN, T), T>>>(cursor, NN);
    fill_k<<<cdiv(EE, T), T>>>(e_dst, rowptr, cursor, eidx);
    // gaussian basis adds into h
    gauss_pre_k<<<cdiv(DD, T), T>>>(g_stds, ginv, gcoef);
    gauss_csr_k<<<cdiv(NN * 32, T), T>>>(edge_dist, rowptr, eidx, g_means, ginv, gcoef,
                                         scale_par, h);

    // --- L layers ---
    for (int l = 0; l < LL; l++) {
        const float* E0 = edge_emb + (size_t)(l * 3 + 0) * 5 * DD;
        const float* E1 = edge_emb + (size_t)(l * 3 + 1) * 5 * DD;
        const float* E2 = edge_emb + (size_t)(l * 3 + 2) * 5 * DD;
        gather_k<<<cdiv(NN * 32, T), T>>>(h, rowptr, eidx, e_src, edge_attr, E0, E1, E2,
                                          mu, istd, bn_gamma + (l - 1) * DD, bn_beta + (l - 1) * DD,
                                          (l > 0) ? 1 : 0, aggh, aggl);
        {
            // w1: Nc=600 -> gemm128 (now ldmatrix)
            dim3 g1(cdiv(D2, 128), cdiv(NN, 128));
            gemm128_k<<<g1, 256, GEMM128_SMEM>>>(aggh, aggl,
                                                 bt1h + (size_t)l * D2 * SP300,
                                                 bt1l + (size_t)l * D2 * SP300,
                                                 mlp_b1 + l * D2, nullptr,
                                                 nullptr, hidh, hidl, NN, D2, SP300, SP600, 1, 0);
            // w2: Nc=300 -> gemm64
            dim3 g2(cdiv(DD, 64), cdiv(NN, 128));
            gemm64_k<<<g2, 128, GEMM64_SMEM>>>(hidh, hidl,
                                               bt2h + (size_t)l * DD * SP600,
                                               bt2l + (size_t)l * DD * SP600,
                                               mlp_b2 + l * DD, nullptr,
                                               h, nullptr, nullptr, NN, DD, SP600, 0, 0, 0);
        }
        bn_stats_k<<<cdiv(NN, BN_RPB), 256>>>(h, stats);
        bn_fin_k<<<cdiv(DD, T), T>>>(stats, mu, istd, stats);
    }

    // --- pooling with inline BN of last layer ---
    gstart_k<<<cdiv(GG + 1, T), T>>>(batch, gstart);
    pool_k<<<GG, 160>>>(h, gstart, mu, istd, bn_gamma + (LL - 1) * DD, bn_beta + (LL - 1) * DD,
                        hgh, hgl);

    // --- head (gemm128) ---
    {
        dim3 g(cdiv(FT, 128), cdiv(GG, 128));
        gemm128_k<<<g, 256, GEMM128_SMEM>>>(hgh, hgl, bt3h, bt3l, feat_b, nullptr,
                                            out_hfeat, hfh, hfl, GG, FT, SP300, SP512, 0, 0);
    }
    {
        dim3 g(cdiv(FT, 128), cdiv(GG, 128));
        gemm128_k<<<g, 256, GEMM128_SMEM>>>(hfh, hfl, bt4h, bt4l, ol_b1, nullptr,
                                            nullptr, tbh, tbl, GG, FT, SP512, SP512, 1, 0);
    }
    {
        dim3 g(cdiv(FT / 2, 128), cdiv(GG, 128));
        gemm128_k<<<g, 256, GEMM128_SMEM>>>(tbh, tbl, bt5h, bt5l, ol_b2, nullptr,
                                            out_final, nullptr, nullptr, GG, FT / 2, SP512, 0, 0, 0);
    }
}